// round 1
// baseline (speedup 1.0000x reference)
#include <cuda_runtime.h>
#include <cuda_bf16.h>
#include <math.h>

// Problem constants
#define BB   2
#define HH   16
#define MM   2048
#define NN   2048
#define DD   2048
#define DH   128
#define DR   64
#define DCAT 192           // DH + DR
#define SCALE_F 0.07216878364870323f   // 1/sqrt(192)

// -------------------- scratch (device globals; sanctioned) --------------------
__device__ float g_Qcat[(long long)BB*HH*MM*DCAT];   // (B,H,M,192)
__device__ float g_Kcat[(long long)BB*HH*NN*DCAT];   // (B,H,N,192)
__device__ float g_V  [(long long)BB*HH*NN*DH];      // (B,H,N,128)
__device__ float g_S  [(long long)BB*HH*MM*NN];      // (B*H, M, N) scores/probs
__device__ float g_Ctx[(long long)BB*MM*HH*DH];      // (B*M, H*128)

// -------------------- epilogue modes --------------------
enum { EPI_PLAIN = 0, EPI_CTX = 1, EPI_CATC = 2, EPI_CATR = 3, EPI_V = 4 };

template<int MODE>
__device__ __forceinline__ void epi_store(float* __restrict__ C, int ldc, long long sC,
                                          int z, int r, int c, float v) {
    if (MODE == EPI_PLAIN) {
        C[(long long)z * sC + (long long)r * ldc + c] = v;
    } else if (MODE == EPI_CTX) {
        // z = b*16+h ; r = m (0..2047) ; c = d (0..127)
        int b = z >> 4, h = z & 15;
        C[((long long)(b * MM + r)) * (HH * DH) + h * DH + c] = v;
    } else if (MODE == EPI_CATC) {
        // r = b*2048+m ; c = h*128+d
        int b = r >> 11, m = r & 2047;
        int h = c >> 7,  d = c & 127;
        C[((long long)((b * HH + h) * MM + m)) * DCAT + d] = v;
    } else if (MODE == EPI_CATR) {
        // r = b*2048+m ; c = h*64+d
        int b = r >> 11, m = r & 2047;
        int h = c >> 6,  d = c & 63;
        C[((long long)((b * HH + h) * MM + m)) * DCAT + DH + d] = v;
    } else { // EPI_V : r = b*2048+n ; c = h*128+d
        int b = r >> 11, n = r & 2047;
        int h = c >> 7,  d = c & 127;
        C[((long long)((b * HH + h) * NN + n)) * DH + d] = v;
    }
}

// -------------------- generic tiled SGEMM: C = A * op(B) --------------------
// A: (M x K) row-major (lda = K-stride). TRANSB: B is (N x K) row-major (x @ W^T).
// !TRANSB: B is (K x N) row-major. All tile dims must divide M,N; K % 8 == 0.
#define BMT 128
#define BNT 128
#define BKT 8

template<int MODE, bool TRANSB>
__global__ void __launch_bounds__(256)
sgemm_kernel(const float* __restrict__ A, int lda, long long sA,
             const float* __restrict__ Bm, int ldb, long long sB,
             float* __restrict__ C, int ldc, long long sC,
             int K)
{
    const int z = blockIdx.z;
    const float* Ab = A  + (long long)z * sA;
    const float* Bb = Bm + (long long)z * sB;

    const int rowBase = blockIdx.y * BMT;
    const int colBase = blockIdx.x * BNT;

    __shared__ float As[BKT][BMT];
    __shared__ float Bs[BKT][BNT];

    const int t  = threadIdx.x;
    const int tx = t & 15;    // 16 cols of threads
    const int ty = t >> 4;    // 16 rows of threads

    float acc[8][8];
    #pragma unroll
    for (int i = 0; i < 8; i++)
        #pragma unroll
        for (int j = 0; j < 8; j++) acc[i][j] = 0.f;

    const int ar  = t >> 1;          // 0..127 row within tile
    const int ac4 = (t & 1) * 4;     // 0 or 4
    const int bk  = t >> 5;          // 0..7  (for !TRANSB)
    const int bc4 = (t & 31) * 4;    // 0..124

    for (int k0 = 0; k0 < K; k0 += BKT) {
        // A tile: 128 rows x 8 k
        float4 av = *(const float4*)(Ab + (long long)(rowBase + ar) * lda + k0 + ac4);
        As[ac4 + 0][ar] = av.x; As[ac4 + 1][ar] = av.y;
        As[ac4 + 2][ar] = av.z; As[ac4 + 3][ar] = av.w;
        if (TRANSB) {
            float4 bv = *(const float4*)(Bb + (long long)(colBase + ar) * ldb + k0 + ac4);
            Bs[ac4 + 0][ar] = bv.x; Bs[ac4 + 1][ar] = bv.y;
            Bs[ac4 + 2][ar] = bv.z; Bs[ac4 + 3][ar] = bv.w;
        } else {
            float4 bv = *(const float4*)(Bb + (long long)(k0 + bk) * ldb + colBase + bc4);
            *(float4*)&Bs[bk][bc4] = bv;
        }
        __syncthreads();

        #pragma unroll
        for (int k = 0; k < BKT; k++) {
            float a[8], b[8];
            const float4* ap = (const float4*)&As[k][ty * 8];
            const float4* bp = (const float4*)&Bs[k][tx * 8];
            float4 a0 = ap[0], a1 = ap[1];
            float4 b0 = bp[0], b1 = bp[1];
            a[0]=a0.x; a[1]=a0.y; a[2]=a0.z; a[3]=a0.w;
            a[4]=a1.x; a[5]=a1.y; a[6]=a1.z; a[7]=a1.w;
            b[0]=b0.x; b[1]=b0.y; b[2]=b0.z; b[3]=b0.w;
            b[4]=b1.x; b[5]=b1.y; b[6]=b1.z; b[7]=b1.w;
            #pragma unroll
            for (int i = 0; i < 8; i++)
                #pragma unroll
                for (int j = 0; j < 8; j++)
                    acc[i][j] = fmaf(a[i], b[j], acc[i][j]);
        }
        __syncthreads();
    }

    #pragma unroll
    for (int i = 0; i < 8; i++) {
        int r = rowBase + ty * 8 + i;
        #pragma unroll
        for (int j = 0; j < 8; j++) {
            int c = colBase + tx * 8 + j;
            epi_store<MODE>(C, ldc, sC, z, r, c, acc[i][j]);
        }
    }
}

// -------------------- RoPE (in-place on R slice of cat buffer) --------------------
__global__ void rope_kernel(float* __restrict__ buf) {
    int idx = blockIdx.x * blockDim.x + threadIdx.x; // B*H*2048*32 threads
    int i  = idx & 31;
    int m  = (idx >> 5) & 2047;
    int bh = idx >> 16;
    float* p = buf + ((long long)(bh * MM + m)) * DCAT + DH + 2 * i;
    double freq = exp(-(double)i / 32.0 * log(1.0e6));
    double ang  = (double)m * freq;
    double s, c;
    sincos(ang, &s, &c);
    float cf = (float)c, sf = (float)s;
    float x0 = p[0], x1 = p[1];
    p[0] = x0 * cf - x1 * sf;
    p[1] = x1 * cf + x0 * sf;
}

// -------------------- row softmax over N=2048 (scale fused on read) --------------------
__global__ void softmax_kernel(float* __restrict__ S) {
    long long row = blockIdx.x;
    float* p = S + row * (long long)NN;
    int t = threadIdx.x;  // 256 threads, 8 elems each
    __shared__ float red[256];

    float v[8];
    float lmax = -INFINITY;
    #pragma unroll
    for (int i = 0; i < 8; i++) {
        v[i] = p[t + 256 * i] * SCALE_F;
        lmax = fmaxf(lmax, v[i]);
    }
    red[t] = lmax; __syncthreads();
    #pragma unroll
    for (int s = 128; s > 0; s >>= 1) {
        if (t < s) red[t] = fmaxf(red[t], red[t + s]);
        __syncthreads();
    }
    float m = red[0];
    __syncthreads();

    float lsum = 0.f;
    #pragma unroll
    for (int i = 0; i < 8; i++) { v[i] = expf(v[i] - m); lsum += v[i]; }
    red[t] = lsum; __syncthreads();
    #pragma unroll
    for (int s = 128; s > 0; s >>= 1) {
        if (t < s) red[t] += red[t + s];
        __syncthreads();
    }
    float inv = 1.f / red[0];
    #pragma unroll
    for (int i = 0; i < 8; i++) p[t + 256 * i] = v[i] * inv;
}

// -------------------- launch --------------------
extern "C" void kernel_launch(void* const* d_in, const int* in_sizes, int n_in,
                              void* d_out, int out_size) {
    const float* query = (const float*)d_in[0];
    const float* kv    = (const float*)d_in[1];
    const float* W_QC  = (const float*)d_in[2];
    const float* W_KC  = (const float*)d_in[3];
    const float* W_QR  = (const float*)d_in[4];
    const float* W_KR  = (const float*)d_in[5];
    const float* W_V   = (const float*)d_in[6];
    const float* W_O   = (const float*)d_in[7];
    float* out = (float*)d_out;

    float *Qcat, *Kcat, *V, *S, *Ctx;
    cudaGetSymbolAddress((void**)&Qcat, g_Qcat);
    cudaGetSymbolAddress((void**)&Kcat, g_Kcat);
    cudaGetSymbolAddress((void**)&V,    g_V);
    cudaGetSymbolAddress((void**)&S,    g_S);
    cudaGetSymbolAddress((void**)&Ctx,  g_Ctx);

    dim3 blk(256);

    // Projections (rows = B*M = 4096), scatter into head-major layouts
    sgemm_kernel<EPI_CATC, true><<<dim3(DD / BNT, (BB * MM) / BMT, 1), blk>>>(
        query, DD, 0, W_QC, DD, 0, Qcat, 0, 0, DD);
    sgemm_kernel<EPI_CATR, true><<<dim3((HH * DR) / BNT, (BB * MM) / BMT, 1), blk>>>(
        query, DD, 0, W_QR, DD, 0, Qcat, 0, 0, DD);
    sgemm_kernel<EPI_CATC, true><<<dim3(DD / BNT, (BB * NN) / BMT, 1), blk>>>(
        kv, DD, 0, W_KC, DD, 0, Kcat, 0, 0, DD);
    sgemm_kernel<EPI_CATR, true><<<dim3((HH * DR) / BNT, (BB * NN) / BMT, 1), blk>>>(
        kv, DD, 0, W_KR, DD, 0, Kcat, 0, 0, DD);
    sgemm_kernel<EPI_V, true><<<dim3(DD / BNT, (BB * NN) / BMT, 1), blk>>>(
        kv, DD, 0, W_V, DD, 0, V, 0, 0, DD);

    // RoPE on R slices
    int rope_threads = BB * HH * MM * 32;   // 2,097,152
    rope_kernel<<<rope_threads / 256, 256>>>(Qcat);
    rope_kernel<<<rope_threads / 256, 256>>>(Kcat);

    // Scores: per (b,h) S = Qcat @ Kcat^T  (K = 192)
    sgemm_kernel<EPI_PLAIN, true><<<dim3(NN / BNT, MM / BMT, BB * HH), blk>>>(
        Qcat, DCAT, (long long)MM * DCAT,
        Kcat, DCAT, (long long)NN * DCAT,
        S, NN, (long long)MM * NN, DCAT);

    // Softmax rows (scale fused)
    softmax_kernel<<<BB * HH * MM, 256>>>(S);

    // PV: per (b,h) Ctx_slice = P (2048x2048) @ V (2048x128)
    sgemm_kernel<EPI_CTX, false><<<dim3(DH / BNT, MM / BMT, BB * HH), blk>>>(
        S, NN, (long long)MM * NN,
        V, DH, (long long)NN * DH,
        Ctx, 0, 0, NN);

    // Output projection: out = Ctx (4096x2048) @ W_O^T (2048x2048)
    sgemm_kernel<EPI_PLAIN, true><<<dim3(DD / BNT, (BB * MM) / BMT, 1), blk>>>(
        Ctx, HH * DH, 0, W_O, DD, 0, out, DD, 0, HH * DH);
}

// round 2
// speedup vs baseline: 3.0881x; 3.0881x over previous
#include <cuda_runtime.h>
#include <cuda_bf16.h>
#include <math.h>
#include <stdint.h>

// Problem constants
#define BB   2
#define HH   16
#define MM   2048
#define NN   2048
#define DD   2048
#define DH   128
#define DR   64
#define DCAT 192
#define SCALE_F 0.07216878364870323f   // 1/sqrt(192)

// -------------------- scratch --------------------
__device__ float g_Qcat[(long long)BB*HH*MM*DCAT];   // (B,H,M,192) tf32-rounded
__device__ float g_Kcat[(long long)BB*HH*NN*DCAT];   // (B,H,N,192) tf32-rounded
__device__ float g_Vt [(long long)BB*HH*DH*NN];      // (B,H,128,N) tf32-rounded (transposed V)
__device__ float g_S  [(long long)BB*HH*MM*NN];      // scores then probs
__device__ float g_Ctx[(long long)BB*MM*HH*DH];      // (B*M, 2048) tf32-rounded
// tf32-rounded copies of inputs
__device__ float g_cq [(long long)BB*MM*DD];
__device__ float g_ckv[(long long)BB*NN*DD];
__device__ float g_wqc[(long long)HH*DH*DD];
__device__ float g_wkc[(long long)HH*DH*DD];
__device__ float g_wqr[(long long)HH*DR*DD];
__device__ float g_wkr[(long long)HH*DR*DD];
__device__ float g_wv [(long long)HH*DH*DD];
__device__ float g_wo [(long long)DD*HH*DH];

// -------------------- helpers --------------------
__device__ __forceinline__ float tf32r(float x) {
    uint32_t u;
    asm("cvt.rna.tf32.f32 %0, %1;" : "=r"(u) : "f"(x));
    return __uint_as_float(u);
}

__device__ __forceinline__ void cp16(void* smem, const void* g) {
    uint32_t s = (uint32_t)__cvta_generic_to_shared(smem);
    asm volatile("cp.async.cg.shared.global [%0], [%1], 16;" :: "r"(s), "l"(g));
}

// -------------------- input conversion --------------------
__global__ void conv_kernel(const float4* __restrict__ in, float4* __restrict__ out, int n4) {
    int i = blockIdx.x * blockDim.x + threadIdx.x;
    if (i < n4) {
        float4 v = in[i];
        v.x = tf32r(v.x); v.y = tf32r(v.y); v.z = tf32r(v.z); v.w = tf32r(v.w);
        out[i] = v;
    }
}

// -------------------- epilogue modes --------------------
enum { EPI_PLAIN = 0, EPI_CTX = 1, EPI_CATC = 2, EPI_CATR = 3, EPI_VT = 4 };

template<int MODE, bool ROUND>
__device__ __forceinline__ void epi_store(float* __restrict__ C, int ldc, long long sC,
                                          int z, int r, int c, float v) {
    if (ROUND) v = tf32r(v);
    if (MODE == EPI_PLAIN) {
        C[(long long)z * sC + (long long)r * ldc + c] = v;
    } else if (MODE == EPI_CTX) {
        int b = z >> 4, h = z & 15;
        C[((long long)(b * MM + r)) * (HH * DH) + h * DH + c] = v;
    } else if (MODE == EPI_CATC) {
        int b = r >> 11, m = r & 2047;
        int h = c >> 7,  d = c & 127;
        C[((long long)((b * HH + h) * MM + m)) * DCAT + d] = v;
    } else if (MODE == EPI_CATR) {
        int b = r >> 11, m = r & 2047;
        int h = c >> 6,  d = c & 63;
        C[((long long)((b * HH + h) * MM + m)) * DCAT + DH + d] = v;
    } else { // EPI_VT : r = b*2048+n ; c = h*128+d  ->  Vt[b,h,d,n]
        int b = r >> 11, n = r & 2047;
        int h = c >> 7,  d = c & 127;
        C[((long long)((b * HH + h) * DH + d)) * NN + n] = v;
    }
}

// -------------------- tf32 tensor-core GEMM: C = A * B^T --------------------
// A: (rows x K) row-major, B: (cols x K) row-major, both tf32-pre-rounded.
// Block tile 128x128, BK=32, 8 warps (2m x 4n), warp tile 64x32.
#define SMSTRIDE 36
#define STAGE_F  (128 * SMSTRIDE)           // floats per tile buffer
#define SMEM_BYTES (4 * STAGE_F * 4)        // 2 stages * (A+B) = 73728 B

template<int MODE, bool ROUND>
__global__ void __launch_bounds__(256, 2)
mma_gemm(const float* __restrict__ A, int lda, long long sA,
         const float* __restrict__ Bm, int ldb, long long sB,
         float* __restrict__ C, int ldc, long long sC, int K)
{
    extern __shared__ float sm[];
    // layout: [stage0 A][stage0 B][stage1 A][stage1 B]
    const int z = blockIdx.z;
    const float* Ab = A  + (long long)z * sA + (long long)blockIdx.y * 128 * lda;
    const float* Bb = Bm + (long long)z * sB + (long long)blockIdx.x * 128 * ldb;

    const int t = threadIdx.x;
    const int lane = t & 31;
    const int warp = t >> 5;
    const int wm = (warp & 1) * 64;
    const int wn = (warp >> 1) * 32;

    const int lr = t >> 3;        // 0..31 (row within 32-row chunk)
    const int lc = (t & 7) * 4;   // float col 0,4,...,28

    float acc[4][4][4];
    #pragma unroll
    for (int i = 0; i < 4; i++)
        #pragma unroll
        for (int j = 0; j < 4; j++)
            #pragma unroll
            for (int q = 0; q < 4; q++) acc[i][j][q] = 0.f;

    const int KT = K >> 5;

    // issue one 128x32 A tile + B tile into stage buf
    auto issue = [&](int kt, int buf) {
        float* Asb = sm + buf * 2 * STAGE_F;
        float* Bsb = Asb + STAGE_F;
        const float* Ag = Ab + kt * 32 + lc;
        const float* Bg = Bb + kt * 32 + lc;
        #pragma unroll
        for (int i = 0; i < 4; i++) {
            int row = lr + 32 * i;
            cp16(&Asb[row * SMSTRIDE + lc], Ag + (long long)row * lda);
            cp16(&Bsb[row * SMSTRIDE + lc], Bg + (long long)row * ldb);
        }
        asm volatile("cp.async.commit_group;" ::: "memory");
    };

    issue(0, 0);

    const int fr = lane >> 2;   // 0..7
    const int fc = lane & 3;    // 0..3

    for (int kt = 0; kt < KT; kt++) {
        if (kt + 1 < KT) {
            issue(kt + 1, (kt + 1) & 1);
            asm volatile("cp.async.wait_group 1;" ::: "memory");
        } else {
            asm volatile("cp.async.wait_group 0;" ::: "memory");
        }
        __syncthreads();

        const float* Asb = sm + (kt & 1) * 2 * STAGE_F;
        const float* Bsb = Asb + STAGE_F;

        #pragma unroll
        for (int ks = 0; ks < 4; ks++) {
            const int k0 = ks * 8;
            uint32_t af[4][4], bf[4][2];
            #pragma unroll
            for (int mi = 0; mi < 4; mi++) {
                int r = wm + mi * 16 + fr;
                af[mi][0] = __float_as_uint(Asb[r * SMSTRIDE + k0 + fc]);
                af[mi][1] = __float_as_uint(Asb[(r + 8) * SMSTRIDE + k0 + fc]);
                af[mi][2] = __float_as_uint(Asb[r * SMSTRIDE + k0 + 4 + fc]);
                af[mi][3] = __float_as_uint(Asb[(r + 8) * SMSTRIDE + k0 + 4 + fc]);
            }
            #pragma unroll
            for (int ni = 0; ni < 4; ni++) {
                int cb = wn + ni * 8 + fr;
                bf[ni][0] = __float_as_uint(Bsb[cb * SMSTRIDE + k0 + fc]);
                bf[ni][1] = __float_as_uint(Bsb[cb * SMSTRIDE + k0 + 4 + fc]);
            }
            #pragma unroll
            for (int mi = 0; mi < 4; mi++)
                #pragma unroll
                for (int ni = 0; ni < 4; ni++) {
                    asm volatile(
                        "mma.sync.aligned.m16n8k8.row.col.f32.tf32.tf32.f32 "
                        "{%0,%1,%2,%3},{%4,%5,%6,%7},{%8,%9},{%0,%1,%2,%3};"
                        : "+f"(acc[mi][ni][0]), "+f"(acc[mi][ni][1]),
                          "+f"(acc[mi][ni][2]), "+f"(acc[mi][ni][3])
                        : "r"(af[mi][0]), "r"(af[mi][1]), "r"(af[mi][2]), "r"(af[mi][3]),
                          "r"(bf[ni][0]), "r"(bf[ni][1]));
                }
        }
        __syncthreads();
    }

    const int rowBase = blockIdx.y * 128;
    const int colBase = blockIdx.x * 128;
    #pragma unroll
    for (int mi = 0; mi < 4; mi++) {
        int r0 = rowBase + wm + mi * 16 + fr;
        #pragma unroll
        for (int ni = 0; ni < 4; ni++) {
            int c0 = colBase + wn + ni * 8 + fc * 2;
            epi_store<MODE, ROUND>(C, ldc, sC, z, r0,     c0,     acc[mi][ni][0]);
            epi_store<MODE, ROUND>(C, ldc, sC, z, r0,     c0 + 1, acc[mi][ni][1]);
            epi_store<MODE, ROUND>(C, ldc, sC, z, r0 + 8, c0,     acc[mi][ni][2]);
            epi_store<MODE, ROUND>(C, ldc, sC, z, r0 + 8, c0 + 1, acc[mi][ni][3]);
        }
    }
}

// -------------------- RoPE (in-place, tf32-rounded output) --------------------
__global__ void rope_kernel(float* __restrict__ buf) {
    int idx = blockIdx.x * blockDim.x + threadIdx.x;
    int i  = idx & 31;
    int m  = (idx >> 5) & 2047;
    int bh = idx >> 16;
    float* p = buf + ((long long)(bh * MM + m)) * DCAT + DH + 2 * i;
    double freq = exp(-(double)i / 32.0 * log(1.0e6));
    double ang  = (double)m * freq;
    double s, c;
    sincos(ang, &s, &c);
    float cf = (float)c, sf = (float)s;
    float x0 = p[0], x1 = p[1];
    p[0] = tf32r(x0 * cf - x1 * sf);
    p[1] = tf32r(x1 * cf + x0 * sf);
}

// -------------------- row softmax over N=2048 (tf32-rounded output) ---------
__global__ void softmax_kernel(float* __restrict__ S) {
    long long row = blockIdx.x;
    float* p = S + row * (long long)NN;
    int t = threadIdx.x;
    __shared__ float red[256];

    float v[8];
    float lmax = -INFINITY;
    #pragma unroll
    for (int i = 0; i < 8; i++) {
        v[i] = p[t + 256 * i] * SCALE_F;
        lmax = fmaxf(lmax, v[i]);
    }
    red[t] = lmax; __syncthreads();
    #pragma unroll
    for (int s = 128; s > 0; s >>= 1) {
        if (t < s) red[t] = fmaxf(red[t], red[t + s]);
        __syncthreads();
    }
    float m = red[0];
    __syncthreads();

    float lsum = 0.f;
    #pragma unroll
    for (int i = 0; i < 8; i++) { v[i] = expf(v[i] - m); lsum += v[i]; }
    red[t] = lsum; __syncthreads();
    #pragma unroll
    for (int s = 128; s > 0; s >>= 1) {
        if (t < s) red[t] += red[t + s];
        __syncthreads();
    }
    float inv = 1.f / red[0];
    #pragma unroll
    for (int i = 0; i < 8; i++) p[t + 256 * i] = tf32r(v[i] * inv);
}

// -------------------- launch --------------------
extern "C" void kernel_launch(void* const* d_in, const int* in_sizes, int n_in,
                              void* d_out, int out_size) {
    const float* query = (const float*)d_in[0];
    const float* kv    = (const float*)d_in[1];
    const float* W_QC  = (const float*)d_in[2];
    const float* W_KC  = (const float*)d_in[3];
    const float* W_QR  = (const float*)d_in[4];
    const float* W_KR  = (const float*)d_in[5];
    const float* W_V   = (const float*)d_in[6];
    const float* W_O   = (const float*)d_in[7];
    float* out = (float*)d_out;

    float *Qcat, *Kcat, *Vt, *S, *Ctx;
    float *cq, *ckv, *wqc, *wkc, *wqr, *wkr, *wv, *wo;
    cudaGetSymbolAddress((void**)&Qcat, g_Qcat);
    cudaGetSymbolAddress((void**)&Kcat, g_Kcat);
    cudaGetSymbolAddress((void**)&Vt,   g_Vt);
    cudaGetSymbolAddress((void**)&S,    g_S);
    cudaGetSymbolAddress((void**)&Ctx,  g_Ctx);
    cudaGetSymbolAddress((void**)&cq,   g_cq);
    cudaGetSymbolAddress((void**)&ckv,  g_ckv);
    cudaGetSymbolAddress((void**)&wqc,  g_wqc);
    cudaGetSymbolAddress((void**)&wkc,  g_wkc);
    cudaGetSymbolAddress((void**)&wqr,  g_wqr);
    cudaGetSymbolAddress((void**)&wkr,  g_wkr);
    cudaGetSymbolAddress((void**)&wv,   g_wv);
    cudaGetSymbolAddress((void**)&wo,   g_wo);

    // allow >48KB dynamic smem (idempotent)
    cudaFuncSetAttribute(mma_gemm<EPI_CATC, true>,  cudaFuncAttributeMaxDynamicSharedMemorySize, SMEM_BYTES);
    cudaFuncSetAttribute(mma_gemm<EPI_CATR, true>,  cudaFuncAttributeMaxDynamicSharedMemorySize, SMEM_BYTES);
    cudaFuncSetAttribute(mma_gemm<EPI_VT,   true>,  cudaFuncAttributeMaxDynamicSharedMemorySize, SMEM_BYTES);
    cudaFuncSetAttribute(mma_gemm<EPI_PLAIN,false>, cudaFuncAttributeMaxDynamicSharedMemorySize, SMEM_BYTES);
    cudaFuncSetAttribute(mma_gemm<EPI_CTX,  true>,  cudaFuncAttributeMaxDynamicSharedMemorySize, SMEM_BYTES);

    // ---- prepass: tf32-round all GEMM inputs ----
    auto conv = [&](const float* src, float* dst, long long n) {
        int n4 = (int)(n / 4);
        conv_kernel<<<(n4 + 255) / 256, 256>>>((const float4*)src, (float4*)dst, n4);
    };
    conv(query, cq,  (long long)BB * MM * DD);
    conv(kv,    ckv, (long long)BB * NN * DD);
    conv(W_QC,  wqc, (long long)HH * DH * DD);
    conv(W_KC,  wkc, (long long)HH * DH * DD);
    conv(W_QR,  wqr, (long long)HH * DR * DD);
    conv(W_KR,  wkr, (long long)HH * DR * DD);
    conv(W_V,   wv,  (long long)HH * DH * DD);
    conv(W_O,   wo,  (long long)DD * HH * DH);

    dim3 blk(256);

    // ---- projections (rows = B*M = 4096) ----
    mma_gemm<EPI_CATC, true><<<dim3(DD / 128, (BB * MM) / 128, 1), blk, SMEM_BYTES>>>(
        cq, DD, 0, wqc, DD, 0, Qcat, 0, 0, DD);
    mma_gemm<EPI_CATR, true><<<dim3((HH * DR) / 128, (BB * MM) / 128, 1), blk, SMEM_BYTES>>>(
        cq, DD, 0, wqr, DD, 0, Qcat, 0, 0, DD);
    mma_gemm<EPI_CATC, true><<<dim3(DD / 128, (BB * NN) / 128, 1), blk, SMEM_BYTES>>>(
        ckv, DD, 0, wkc, DD, 0, Kcat, 0, 0, DD);
    mma_gemm<EPI_CATR, true><<<dim3((HH * DR) / 128, (BB * NN) / 128, 1), blk, SMEM_BYTES>>>(
        ckv, DD, 0, wkr, DD, 0, Kcat, 0, 0, DD);
    mma_gemm<EPI_VT, true><<<dim3(DD / 128, (BB * NN) / 128, 1), blk, SMEM_BYTES>>>(
        ckv, DD, 0, wv, DD, 0, Vt, 0, 0, DD);

    // ---- RoPE on R slices ----
    int rope_threads = BB * HH * MM * 32;
    rope_kernel<<<rope_threads / 256, 256>>>(Qcat);
    rope_kernel<<<rope_threads / 256, 256>>>(Kcat);

    // ---- scores: per (b,h)  S = Qcat @ Kcat^T  (K = 192) ----
    mma_gemm<EPI_PLAIN, false><<<dim3(NN / 128, MM / 128, BB * HH), blk, SMEM_BYTES>>>(
        Qcat, DCAT, (long long)MM * DCAT,
        Kcat, DCAT, (long long)NN * DCAT,
        S, NN, (long long)MM * NN, DCAT);

    // ---- softmax ----
    softmax_kernel<<<BB * HH * MM, 256>>>(S);

    // ---- PV: per (b,h)  Ctx = P (2048x2048) @ Vt^T (Vt is 128x2048) ----
    mma_gemm<EPI_CTX, true><<<dim3(1, MM / 128, BB * HH), blk, SMEM_BYTES>>>(
        S, NN, (long long)MM * NN,
        Vt, NN, (long long)DH * NN,
        Ctx, 0, 0, NN);

    // ---- output projection: out = Ctx (4096x2048) @ W_O^T ----
    mma_gemm<EPI_PLAIN, false><<<dim3(DD / 128, (BB * MM) / 128, 1), blk, SMEM_BYTES>>>(
        Ctx, HH * DH, 0, wo, DD, 0, out, DD, 0, HH * DH);
}

// round 4
// speedup vs baseline: 3.3530x; 1.0858x over previous
#include <cuda_runtime.h>
#include <cuda_bf16.h>
#include <math.h>
#include <stdint.h>

// Problem constants
#define BB   2
#define HH   16
#define MM   2048
#define NN   2048
#define DD   2048
#define DH   128
#define DR   64
#define DCAT 192
#define SCALE_F 0.07216878364870323f   // 1/sqrt(192)

// -------------------- scratch --------------------
__device__ float g_Qcat[(long long)BB*HH*MM*DCAT];   // (B,H,M,192) tf32-rounded + RoPE
__device__ float g_Kcat[(long long)BB*HH*NN*DCAT];   // (B,H,N,192)
__device__ float g_Vt [(long long)BB*HH*DH*NN];      // (B,H,128,N) transposed V
__device__ float g_Ctx[(long long)BB*MM*HH*DH];      // (B*M, 2048) tf32-rounded
__device__ float g_cq [(long long)BB*MM*DD];
__device__ float g_ckv[(long long)BB*NN*DD];
__device__ float g_wqc[(long long)HH*DH*DD];
__device__ float g_wkc[(long long)HH*DH*DD];
__device__ float g_wqr[(long long)HH*DR*DD];
__device__ float g_wkr[(long long)HH*DR*DD];
__device__ float g_wv [(long long)HH*DH*DD];
__device__ float g_wo [(long long)DD*HH*DH];

// -------------------- helpers --------------------
__device__ __forceinline__ float tf32r(float x) {
    uint32_t u;
    asm("cvt.rna.tf32.f32 %0, %1;" : "=r"(u) : "f"(x));
    return __uint_as_float(u);
}
__device__ __forceinline__ void cp16(void* smem, const void* g) {
    uint32_t s = (uint32_t)__cvta_generic_to_shared(smem);
    asm volatile("cp.async.cg.shared.global [%0], [%1], 16;" :: "r"(s), "l"(g));
}
#define CP_COMMIT() asm volatile("cp.async.commit_group;" ::: "memory")
#define CP_WAIT(n)  asm volatile("cp.async.wait_group %0;" :: "n"(n) : "memory")

__device__ __forceinline__ void mma_tf32(float acc[4],
        uint32_t a0, uint32_t a1, uint32_t a2, uint32_t a3,
        uint32_t b0, uint32_t b1) {
    asm volatile(
        "mma.sync.aligned.m16n8k8.row.col.f32.tf32.tf32.f32 "
        "{%0,%1,%2,%3},{%4,%5,%6,%7},{%8,%9},{%0,%1,%2,%3};"
        : "+f"(acc[0]), "+f"(acc[1]), "+f"(acc[2]), "+f"(acc[3])
        : "r"(a0), "r"(a1), "r"(a2), "r"(a3), "r"(b0), "r"(b1));
}

// -------------------- merged input conversion (1 launch) --------------------
struct ConvArgs {
    const float4* src[8];
    float4*       dst[8];
    int           n4[8];
};
__global__ void conv8_kernel(ConvArgs a) {
    int seg = blockIdx.y;
    int i = blockIdx.x * blockDim.x + threadIdx.x;
    if (i < a.n4[seg]) {
        float4 v = a.src[seg][i];
        v.x = tf32r(v.x); v.y = tf32r(v.y); v.z = tf32r(v.z); v.w = tf32r(v.w);
        a.dst[seg][i] = v;
    }
}

// -------------------- epilogue modes --------------------
enum { EPI_PLAIN = 0, EPI_CATC = 2, EPI_CATR = 3, EPI_VT = 4 };

template<int MODE, bool ROUND>
__device__ __forceinline__ void epi_store(float* __restrict__ C, int ldc, long long sC,
                                          int z, int r, int c, float v) {
    if (ROUND) v = tf32r(v);
    if (MODE == EPI_PLAIN) {
        C[(long long)z * sC + (long long)r * ldc + c] = v;
    } else if (MODE == EPI_CATC) {
        int b = r >> 11, m = r & 2047;
        int h = c >> 7,  d = c & 127;
        C[((long long)((b * HH + h) * MM + m)) * DCAT + d] = v;
    } else if (MODE == EPI_CATR) {
        int b = r >> 11, m = r & 2047;
        int h = c >> 6,  d = c & 63;
        C[((long long)((b * HH + h) * MM + m)) * DCAT + DH + d] = v;
    } else { // EPI_VT
        int b = r >> 11, n = r & 2047;
        int h = c >> 7,  d = c & 127;
        C[((long long)((b * HH + h) * DH + d)) * NN + n] = v;
    }
}

// -------------------- tf32 tensor-core GEMM: C = A * B^T --------------------
#define SMSTRIDE 36
#define STAGE_F  (128 * SMSTRIDE)
#define SMEM_BYTES (4 * STAGE_F * 4)

template<int MODE, bool ROUND>
__global__ void __launch_bounds__(256, 2)
mma_gemm(const float* __restrict__ A, int lda, long long sA,
         const float* __restrict__ Bm, int ldb, long long sB,
         float* __restrict__ C, int ldc, long long sC, int K)
{
    extern __shared__ float sm[];
    const int z = blockIdx.z;
    const float* Ab = A  + (long long)z * sA + (long long)blockIdx.y * 128 * lda;
    const float* Bb = Bm + (long long)z * sB + (long long)blockIdx.x * 128 * ldb;

    const int t = threadIdx.x;
    const int lane = t & 31;
    const int warp = t >> 5;
    const int wm = (warp & 1) * 64;
    const int wn = (warp >> 1) * 32;
    const int lr = t >> 3;
    const int lc = (t & 7) * 4;

    float acc[4][4][4];
    #pragma unroll
    for (int i = 0; i < 4; i++)
        #pragma unroll
        for (int j = 0; j < 4; j++)
            #pragma unroll
            for (int q = 0; q < 4; q++) acc[i][j][q] = 0.f;

    const int KT = K >> 5;

    auto issue = [&](int kt, int buf) {
        float* Asb = sm + buf * 2 * STAGE_F;
        float* Bsb = Asb + STAGE_F;
        const float* Ag = Ab + kt * 32 + lc;
        const float* Bg = Bb + kt * 32 + lc;
        #pragma unroll
        for (int i = 0; i < 4; i++) {
            int row = lr + 32 * i;
            cp16(&Asb[row * SMSTRIDE + lc], Ag + (long long)row * lda);
            cp16(&Bsb[row * SMSTRIDE + lc], Bg + (long long)row * ldb);
        }
        CP_COMMIT();
    };

    issue(0, 0);
    const int fr = lane >> 2;
    const int fc = lane & 3;

    for (int kt = 0; kt < KT; kt++) {
        if (kt + 1 < KT) { issue(kt + 1, (kt + 1) & 1); CP_WAIT(1); }
        else             { CP_WAIT(0); }
        __syncthreads();

        const float* Asb = sm + (kt & 1) * 2 * STAGE_F;
        const float* Bsb = Asb + STAGE_F;

        #pragma unroll
        for (int ks = 0; ks < 4; ks++) {
            const int k0 = ks * 8;
            uint32_t af[4][4], bf[4][2];
            #pragma unroll
            for (int mi = 0; mi < 4; mi++) {
                int r = wm + mi * 16 + fr;
                af[mi][0] = __float_as_uint(Asb[r * SMSTRIDE + k0 + fc]);
                af[mi][1] = __float_as_uint(Asb[(r + 8) * SMSTRIDE + k0 + fc]);
                af[mi][2] = __float_as_uint(Asb[r * SMSTRIDE + k0 + 4 + fc]);
                af[mi][3] = __float_as_uint(Asb[(r + 8) * SMSTRIDE + k0 + 4 + fc]);
            }
            #pragma unroll
            for (int ni = 0; ni < 4; ni++) {
                int cb = wn + ni * 8 + fr;
                bf[ni][0] = __float_as_uint(Bsb[cb * SMSTRIDE + k0 + fc]);
                bf[ni][1] = __float_as_uint(Bsb[cb * SMSTRIDE + k0 + 4 + fc]);
            }
            #pragma unroll
            for (int mi = 0; mi < 4; mi++)
                #pragma unroll
                for (int ni = 0; ni < 4; ni++)
                    mma_tf32(acc[mi][ni], af[mi][0], af[mi][1], af[mi][2], af[mi][3],
                             bf[ni][0], bf[ni][1]);
        }
        __syncthreads();
    }

    const int rowBase = blockIdx.y * 128;
    const int colBase = blockIdx.x * 128;
    #pragma unroll
    for (int mi = 0; mi < 4; mi++) {
        int r0 = rowBase + wm + mi * 16 + fr;
        #pragma unroll
        for (int ni = 0; ni < 4; ni++) {
            int c0 = colBase + wn + ni * 8 + fc * 2;
            epi_store<MODE, ROUND>(C, ldc, sC, z, r0,     c0,     acc[mi][ni][0]);
            epi_store<MODE, ROUND>(C, ldc, sC, z, r0,     c0 + 1, acc[mi][ni][1]);
            epi_store<MODE, ROUND>(C, ldc, sC, z, r0 + 8, c0,     acc[mi][ni][2]);
            epi_store<MODE, ROUND>(C, ldc, sC, z, r0 + 8, c0 + 1, acc[mi][ni][3]);
        }
    }
}

// -------------------- RoPE --------------------
__global__ void rope_kernel(float* __restrict__ buf) {
    int idx = blockIdx.x * blockDim.x + threadIdx.x;
    int i  = idx & 31;
    int m  = (idx >> 5) & 2047;
    int bh = idx >> 16;
    float* p = buf + ((long long)(bh * MM + m)) * DCAT + DH + 2 * i;
    double freq = exp(-(double)i / 32.0 * log(1.0e6));
    double ang  = (double)m * freq;
    double s, c;
    sincos(ang, &s, &c);
    float cf = (float)c, sf = (float)s;
    float x0 = p[0], x1 = p[1];
    p[0] = tf32r(x0 * cf - x1 * sf);
    p[1] = tf32r(x1 * cf + x0 * sf);
}

// -------------------- fused flash attention --------------------
// CTA: 128 Q-rows of one (b,h). smem: Q 128x196 | K 2x128x36 | V 128x132.
#define FQ_STRIDE 196
#define FK_STRIDE 36
#define FV_STRIDE 132
#define FQ_F (128 * FQ_STRIDE)            // 25088 floats
#define FK_F (128 * FK_STRIDE)            // 4608 floats per stage
#define FL_SMEM_BYTES ((FQ_F + 2 * FK_F + 128 * FV_STRIDE) * 4)   // 204800 B

__global__ void __launch_bounds__(256)
flash_kernel(const float* __restrict__ Q, const float* __restrict__ Kc,
             const float* __restrict__ Vt, float* __restrict__ Ctx)
{
    extern __shared__ float sm[];
    float* Qs = sm;
    float* Ks = sm + FQ_F;
    float* Vs = sm + FQ_F + 2 * FK_F;

    const int bh = blockIdx.y;
    const int m0 = blockIdx.x * 128;
    const int t = threadIdx.x;
    const int lane = t & 31;
    const int warp = t >> 5;
    const int fr = lane >> 2;
    const int fc = lane & 3;
    const int rw = warp * 16;

    const float* Qg = Q  + ((long long)bh * MM + m0) * DCAT;
    const float* Kg = Kc + (long long)bh * NN * DCAT;
    const float* Vg = Vt + (long long)bh * DH * NN;

    // issue Q (group)
    #pragma unroll
    for (int i = 0; i < 24; i++) {
        int id = t + 256 * i;
        int r = id / 48, c = (id % 48) * 4;
        cp16(&Qs[r * FQ_STRIDE + c], Qg + (long long)r * DCAT + c);
    }
    CP_COMMIT();

    auto issueK = [&](int n0, int ksub, int buf) {
        float* dst = Ks + buf * FK_F;
        #pragma unroll
        for (int i = 0; i < 4; i++) {
            int id = t + 256 * i;
            int r = id >> 3, c = (id & 7) * 4;
            cp16(&dst[r * FK_STRIDE + c],
                 Kg + (long long)(n0 + r) * DCAT + ksub * 32 + c);
        }
    };
    auto issueV = [&](int n0) {
        #pragma unroll
        for (int i = 0; i < 16; i++) {
            int id = t + 256 * i;
            int r = id >> 5, c = (id & 31) * 4;
            cp16(&Vs[r * FV_STRIDE + c], Vg + (long long)r * NN + n0 + c);
        }
    };

    issueK(0, 0, 0); issueV(0); CP_COMMIT();
    issueK(0, 1, 1); CP_COMMIT();

    float sacc[16][4], oacc[16][4];
    float mrun[2] = { -INFINITY, -INFINITY };
    float lrun[2] = { 0.f, 0.f };
    #pragma unroll
    for (int i = 0; i < 16; i++)
        #pragma unroll
        for (int q = 0; q < 4; q++) oacc[i][q] = 0.f;

    for (int chunk = 0; chunk < 16; chunk++) {
        const int n0 = chunk * 128;
        #pragma unroll
        for (int i = 0; i < 16; i++)
            #pragma unroll
            for (int q = 0; q < 4; q++) sacc[i][q] = 0.f;

        // ---- S = Q @ K^T over 6 k-subchunks of 32 ----
        for (int ksub = 0; ksub < 6; ksub++) {
            if (ksub < 5) { CP_WAIT(1); } else { CP_WAIT(0); }
            __syncthreads();
            const float* Kb = Ks + (ksub & 1) * FK_F;
            #pragma unroll
            for (int kk = 0; kk < 4; kk++) {
                int qc = ksub * 32 + kk * 8 + fc;
                uint32_t a0 = __float_as_uint(Qs[(rw + fr) * FQ_STRIDE + qc]);
                uint32_t a1 = __float_as_uint(Qs[(rw + 8 + fr) * FQ_STRIDE + qc]);
                uint32_t a2 = __float_as_uint(Qs[(rw + fr) * FQ_STRIDE + qc + 4]);
                uint32_t a3 = __float_as_uint(Qs[(rw + 8 + fr) * FQ_STRIDE + qc + 4]);
                #pragma unroll
                for (int ni = 0; ni < 16; ni++) {
                    uint32_t b0 = __float_as_uint(Kb[(8 * ni + fr) * FK_STRIDE + kk * 8 + fc]);
                    uint32_t b1 = __float_as_uint(Kb[(8 * ni + fr) * FK_STRIDE + kk * 8 + fc + 4]);
                    mma_tf32(sacc[ni], a0, a1, a2, a3, b0, b1);
                }
            }
            __syncthreads();
            if (ksub + 2 < 6) { issueK(n0, ksub + 2, ksub & 1); CP_COMMIT(); }
        }

        // ---- online softmax (warp-local; quad shuffles across fc) ----
        #pragma unroll
        for (int i = 0; i < 16; i++)
            #pragma unroll
            for (int q = 0; q < 4; q++) sacc[i][q] *= SCALE_F;

        #pragma unroll
        for (int h = 0; h < 2; h++) {
            float cm = -INFINITY;
            #pragma unroll
            for (int ni = 0; ni < 16; ni++)
                cm = fmaxf(cm, fmaxf(sacc[ni][2 * h], sacc[ni][2 * h + 1]));
            cm = fmaxf(cm, __shfl_xor_sync(0xFFFFFFFF, cm, 1));
            cm = fmaxf(cm, __shfl_xor_sync(0xFFFFFFFF, cm, 2));
            float mnew = fmaxf(mrun[h], cm);
            float alpha = __expf(mrun[h] - mnew);
            mrun[h] = mnew;
            float rs = 0.f;
            #pragma unroll
            for (int ni = 0; ni < 16; ni++) {
                float p0 = __expf(sacc[ni][2 * h] - mnew);
                float p1 = __expf(sacc[ni][2 * h + 1] - mnew);
                rs += p0 + p1;
                sacc[ni][2 * h]     = tf32r(p0);
                sacc[ni][2 * h + 1] = tf32r(p1);
            }
            rs += __shfl_xor_sync(0xFFFFFFFF, rs, 1);
            rs += __shfl_xor_sync(0xFFFFFFFF, rs, 2);
            lrun[h] = lrun[h] * alpha + rs;
            #pragma unroll
            for (int ni = 0; ni < 16; ni++) {
                oacc[ni][2 * h]     *= alpha;
                oacc[ni][2 * h + 1] *= alpha;
            }
        }

        // ---- O += P @ V (P acc-frags -> A-frags via quad shuffles) ----
        #pragma unroll
        for (int s = 0; s < 16; s++) {
            int srcA = (fr << 2) | (fc >> 1);
            int srcB = srcA + 2;
            float x0 = __shfl_sync(0xFFFFFFFF, sacc[s][0], srcA);
            float x1 = __shfl_sync(0xFFFFFFFF, sacc[s][1], srcA);
            float y0 = __shfl_sync(0xFFFFFFFF, sacc[s][0], srcB);
            float y1 = __shfl_sync(0xFFFFFFFF, sacc[s][1], srcB);
            float z0 = __shfl_sync(0xFFFFFFFF, sacc[s][2], srcA);
            float z1 = __shfl_sync(0xFFFFFFFF, sacc[s][3], srcA);
            float w0 = __shfl_sync(0xFFFFFFFF, sacc[s][2], srcB);
            float w1 = __shfl_sync(0xFFFFFFFF, sacc[s][3], srcB);
            bool odd = (fc & 1);
            uint32_t a0 = __float_as_uint(odd ? x1 : x0);   // P[fr][fc]
            uint32_t a2 = __float_as_uint(odd ? y1 : y0);   // P[fr][fc+4]
            uint32_t a1 = __float_as_uint(odd ? z1 : z0);   // P[fr+8][fc]
            uint32_t a3 = __float_as_uint(odd ? w1 : w0);   // P[fr+8][fc+4]
            #pragma unroll
            for (int nj = 0; nj < 16; nj++) {
                uint32_t b0 = __float_as_uint(Vs[(8 * nj + fr) * FV_STRIDE + 8 * s + fc]);
                uint32_t b1 = __float_as_uint(Vs[(8 * nj + fr) * FV_STRIDE + 8 * s + fc + 4]);
                mma_tf32(oacc[nj], a0, a1, a2, a3, b0, b1);
            }
        }
        __syncthreads();
        if (chunk + 1 < 16) {
            issueK(n0 + 128, 0, 0); issueV(n0 + 128); CP_COMMIT();
            issueK(n0 + 128, 1, 1); CP_COMMIT();
        }
    }

    // ---- epilogue: O /= l, scatter into Ctx (B*M, H*128), tf32-rounded ----
    const int b  = bh >> 4;
    const int hd = bh & 15;
    float inv0 = 1.f / lrun[0];
    float inv1 = 1.f / lrun[1];
    int r0 = m0 + rw + fr;
    #pragma unroll
    for (int nj = 0; nj < 16; nj++) {
        int d = hd * DH + nj * 8 + 2 * fc;
        long long base0 = ((long long)(b * MM + r0)) * (HH * DH) + d;
        long long base1 = ((long long)(b * MM + r0 + 8)) * (HH * DH) + d;
        Ctx[base0]     = tf32r(oacc[nj][0] * inv0);
        Ctx[base0 + 1] = tf32r(oacc[nj][1] * inv0);
        Ctx[base1]     = tf32r(oacc[nj][2] * inv1);
        Ctx[base1 + 1] = tf32r(oacc[nj][3] * inv1);
    }
}

// -------------------- launch --------------------
extern "C" void kernel_launch(void* const* d_in, const int* in_sizes, int n_in,
                              void* d_out, int out_size) {
    const float* query = (const float*)d_in[0];
    const float* kv    = (const float*)d_in[1];
    const float* W_QC  = (const float*)d_in[2];
    const float* W_KC  = (const float*)d_in[3];
    const float* W_QR  = (const float*)d_in[4];
    const float* W_KR  = (const float*)d_in[5];
    const float* W_V   = (const float*)d_in[6];
    const float* W_O   = (const float*)d_in[7];
    float* out = (float*)d_out;

    float *Qcat, *Kcat, *Vt, *Ctx;
    float *cq, *ckv, *wqc, *wkc, *wqr, *wkr, *wv, *wo;
    cudaGetSymbolAddress((void**)&Qcat, g_Qcat);
    cudaGetSymbolAddress((void**)&Kcat, g_Kcat);
    cudaGetSymbolAddress((void**)&Vt,   g_Vt);
    cudaGetSymbolAddress((void**)&Ctx,  g_Ctx);
    cudaGetSymbolAddress((void**)&cq,   g_cq);
    cudaGetSymbolAddress((void**)&ckv,  g_ckv);
    cudaGetSymbolAddress((void**)&wqc,  g_wqc);
    cudaGetSymbolAddress((void**)&wkc,  g_wkc);
    cudaGetSymbolAddress((void**)&wqr,  g_wqr);
    cudaGetSymbolAddress((void**)&wkr,  g_wkr);
    cudaGetSymbolAddress((void**)&wv,   g_wv);
    cudaGetSymbolAddress((void**)&wo,   g_wo);

    cudaFuncSetAttribute(mma_gemm<EPI_CATC, true>,  cudaFuncAttributeMaxDynamicSharedMemorySize, SMEM_BYTES);
    cudaFuncSetAttribute(mma_gemm<EPI_CATR, true>,  cudaFuncAttributeMaxDynamicSharedMemorySize, SMEM_BYTES);
    cudaFuncSetAttribute(mma_gemm<EPI_VT,   true>,  cudaFuncAttributeMaxDynamicSharedMemorySize, SMEM_BYTES);
    cudaFuncSetAttribute(mma_gemm<EPI_PLAIN,false>, cudaFuncAttributeMaxDynamicSharedMemorySize, SMEM_BYTES);
    cudaFuncSetAttribute(flash_kernel, cudaFuncAttributeMaxDynamicSharedMemorySize, FL_SMEM_BYTES);

    // ---- single merged tf32-round prepass ----
    ConvArgs ca;
    ca.src[0] = (const float4*)query; ca.dst[0] = (float4*)cq;  ca.n4[0] = BB*MM*DD/4;
    ca.src[1] = (const float4*)kv;    ca.dst[1] = (float4*)ckv; ca.n4[1] = BB*NN*DD/4;
    ca.src[2] = (const float4*)W_QC;  ca.dst[2] = (float4*)wqc; ca.n4[2] = HH*DH*DD/4;
    ca.src[3] = (const float4*)W_KC;  ca.dst[3] = (float4*)wkc; ca.n4[3] = HH*DH*DD/4;
    ca.src[4] = (const float4*)W_QR;  ca.dst[4] = (float4*)wqr; ca.n4[4] = HH*DR*DD/4;
    ca.src[5] = (const float4*)W_KR;  ca.dst[5] = (float4*)wkr; ca.n4[5] = HH*DR*DD/4;
    ca.src[6] = (const float4*)W_V;   ca.dst[6] = (float4*)wv;  ca.n4[6] = HH*DH*DD/4;
    ca.src[7] = (const float4*)W_O;   ca.dst[7] = (float4*)wo;  ca.n4[7] = DD*HH*DH/4;
    {
        int maxn4 = BB*MM*DD/4;
        conv8_kernel<<<dim3((maxn4 + 255) / 256, 8), 256>>>(ca);
    }

    dim3 blk(256);

    // ---- projections ----
    mma_gemm<EPI_CATC, true><<<dim3(DD / 128, (BB * MM) / 128, 1), blk, SMEM_BYTES>>>(
        cq, DD, 0, wqc, DD, 0, Qcat, 0, 0, DD);
    mma_gemm<EPI_CATR, true><<<dim3((HH * DR) / 128, (BB * MM) / 128, 1), blk, SMEM_BYTES>>>(
        cq, DD, 0, wqr, DD, 0, Qcat, 0, 0, DD);
    mma_gemm<EPI_CATC, true><<<dim3(DD / 128, (BB * NN) / 128, 1), blk, SMEM_BYTES>>>(
        ckv, DD, 0, wkc, DD, 0, Kcat, 0, 0, DD);
    mma_gemm<EPI_CATR, true><<<dim3((HH * DR) / 128, (BB * NN) / 128, 1), blk, SMEM_BYTES>>>(
        ckv, DD, 0, wkr, DD, 0, Kcat, 0, 0, DD);
    mma_gemm<EPI_VT, true><<<dim3(DD / 128, (BB * NN) / 128, 1), blk, SMEM_BYTES>>>(
        ckv, DD, 0, wv, DD, 0, Vt, 0, 0, DD);

    // ---- RoPE ----
    int rope_threads = BB * HH * MM * 32;
    rope_kernel<<<rope_threads / 256, 256>>>(Qcat);
    rope_kernel<<<rope_threads / 256, 256>>>(Kcat);

    // ---- fused flash attention: scores + softmax + PV -> Ctx ----
    flash_kernel<<<dim3(MM / 128, BB * HH), blk, FL_SMEM_BYTES>>>(Qcat, Kcat, Vt, Ctx);

    // ---- output projection ----
    mma_gemm<EPI_PLAIN, false><<<dim3(DD / 128, (BB * MM) / 128, 1), blk, SMEM_BYTES>>>(
        Ctx, HH * DH, 0, wo, DD, 0, out, DD, 0, HH * DH);
}

// round 6
// speedup vs baseline: 3.5966x; 1.0727x over previous
#include <cuda_runtime.h>
#include <cuda_bf16.h>
#include <math.h>
#include <stdint.h>

// Problem constants
#define BB   2
#define HH   16
#define MM   2048
#define NN   2048
#define DD   2048
#define DH   128
#define DR   64
#define DCAT 192
#define SCALE_F 0.07216878364870323f   // 1/sqrt(192)

// -------------------- scratch --------------------
__device__ float g_Qcat[(long long)BB*HH*MM*DCAT];   // (B,H,M,192) tf32-rounded + RoPE
__device__ float g_Kcat[(long long)BB*HH*NN*DCAT];   // (B,H,N,192)
__device__ float g_Vt [(long long)BB*HH*DH*NN];      // (B,H,128,N) transposed V
__device__ float g_Ctx[(long long)BB*MM*HH*DH];      // (B*M, 2048) tf32-rounded
__device__ float g_cq [(long long)BB*MM*DD];
__device__ float g_ckv[(long long)BB*NN*DD];
__device__ float g_wqc[(long long)HH*DH*DD];
__device__ float g_wkc[(long long)HH*DH*DD];
__device__ float g_wqr[(long long)HH*DR*DD];
__device__ float g_wkr[(long long)HH*DR*DD];
__device__ float g_wv [(long long)HH*DH*DD];
__device__ float g_wo [(long long)DD*HH*DH];

// -------------------- helpers --------------------
__device__ __forceinline__ float tf32r(float x) {
    uint32_t u;
    asm("cvt.rna.tf32.f32 %0, %1;" : "=r"(u) : "f"(x));
    return __uint_as_float(u);
}
__device__ __forceinline__ void cp16(void* smem, const void* g) {
    uint32_t s = (uint32_t)__cvta_generic_to_shared(smem);
    asm volatile("cp.async.cg.shared.global [%0], [%1], 16;" :: "r"(s), "l"(g));
}
#define CP_COMMIT() asm volatile("cp.async.commit_group;" ::: "memory")
#define CP_WAIT(n)  asm volatile("cp.async.wait_group %0;" :: "n"(n) : "memory")

__device__ __forceinline__ void mma_tf32(float acc[4],
        uint32_t a0, uint32_t a1, uint32_t a2, uint32_t a3,
        uint32_t b0, uint32_t b1) {
    asm volatile(
        "mma.sync.aligned.m16n8k8.row.col.f32.tf32.tf32.f32 "
        "{%0,%1,%2,%3},{%4,%5,%6,%7},{%8,%9},{%0,%1,%2,%3};"
        : "+f"(acc[0]), "+f"(acc[1]), "+f"(acc[2]), "+f"(acc[3])
        : "r"(a0), "r"(a1), "r"(a2), "r"(a3), "r"(b0), "r"(b1));
}

__device__ __forceinline__ void ldm_x4(uint32_t r[4], uint32_t saddr) {
    asm volatile("ldmatrix.sync.aligned.m8n8.x4.shared.b16 {%0,%1,%2,%3}, [%4];"
                 : "=r"(r[0]), "=r"(r[1]), "=r"(r[2]), "=r"(r[3]) : "r"(saddr));
}

// -------------------- merged input conversion (1 launch) --------------------
struct ConvArgs {
    const float4* src[8];
    float4*       dst[8];
    int           n4[8];
};
__global__ void conv8_kernel(ConvArgs a) {
    int seg = blockIdx.y;
    int i = blockIdx.x * blockDim.x + threadIdx.x;
    if (i < a.n4[seg]) {
        float4 v = a.src[seg][i];
        v.x = tf32r(v.x); v.y = tf32r(v.y); v.z = tf32r(v.z); v.w = tf32r(v.w);
        a.dst[seg][i] = v;
    }
}

// -------------------- epilogue modes --------------------
enum { EPI_PLAIN = 0, EPI_CATC = 2, EPI_CATR = 3, EPI_VT = 4 };

template<int MODE, bool ROUND>
__device__ __forceinline__ void epi_store(float* __restrict__ C, int ldc,
                                          int r, int c, float v) {
    if (ROUND) v = tf32r(v);
    if (MODE == EPI_PLAIN) {
        C[(long long)r * ldc + c] = v;
    } else if (MODE == EPI_CATC) {
        int b = r >> 11, m = r & 2047;
        int h = c >> 7,  d = c & 127;
        C[((long long)((b * HH + h) * MM + m)) * DCAT + d] = v;
    } else if (MODE == EPI_CATR) {
        int b = r >> 11, m = r & 2047;
        int h = c >> 6,  d = c & 63;
        C[((long long)((b * HH + h) * MM + m)) * DCAT + DH + d] = v;
    } else { // EPI_VT : r = b*2048+n ; c = h*128+d -> Vt[b,h,d,n]
        int b = r >> 11, n = r & 2047;
        int h = c >> 7,  d = c & 127;
        C[((long long)((b * HH + h) * DH + d)) * NN + n] = v;
    }
}

// -------------------- tf32 mma.sync GEMM: C = A * B^T --------------------
// 128x128 CTA tile, 4 warps (2x2), warp tile 64x64, BK=32, double-buffered
// cp.async, ldmatrix.x4 fragment loads. A:(rows x K), B:(cols x K) row-major.
#define SMSTRIDE 36
#define STAGE_F  (128 * SMSTRIDE)
#define SMEM_BYTES (4 * STAGE_F * 4)        // 73728 B

template<int MODE, bool ROUND>
__global__ void __launch_bounds__(128)
mma_gemm(const float* __restrict__ A, int lda,
         const float* __restrict__ Bm, int ldb,
         float* __restrict__ C, int ldc, int K)
{
    extern __shared__ float sm[];
    const float* Ab = A  + (long long)blockIdx.y * 128 * lda;
    const float* Bb = Bm + (long long)blockIdx.x * 128 * ldb;

    const int t = threadIdx.x;
    const int lane = t & 31;
    const int warp = t >> 5;
    const int wm = (warp & 1) * 64;
    const int wn = (warp >> 1) * 64;

    // ldmatrix per-lane addressing
    const int lrow = lane & 7;
    const int lsel = lane >> 3;          // 0..3
    const int a_row = lrow + (lsel & 1) * 8;          // within 16-row tile
    const int a_col = (lsel >> 1) * 4;                // 0 or 4
    const int b_row = lrow + (lsel >> 1) * 8;         // within 16-row (2 ni) tile
    const int b_col = (lsel & 1) * 4;

    const uint32_t smem0 = (uint32_t)__cvta_generic_to_shared(sm);

    float acc[4][8][4];
    #pragma unroll
    for (int i = 0; i < 4; i++)
        #pragma unroll
        for (int j = 0; j < 8; j++)
            #pragma unroll
            for (int q = 0; q < 4; q++) acc[i][j][q] = 0.f;

    const int KT = K >> 5;

    auto issue = [&](int kt, int buf) {
        float* Asb = sm + buf * 2 * STAGE_F;
        float* Bsb = Asb + STAGE_F;
        const float* Ag = Ab + kt * 32;
        const float* Bg = Bb + kt * 32;
        #pragma unroll
        for (int i = 0; i < 8; i++) {
            int id = t + 128 * i;
            int row = id >> 3, cc = (id & 7) * 4;
            cp16(&Asb[row * SMSTRIDE + cc], Ag + (long long)row * lda + cc);
            cp16(&Bsb[row * SMSTRIDE + cc], Bg + (long long)row * ldb + cc);
        }
        CP_COMMIT();
    };

    issue(0, 0);

    for (int kt = 0; kt < KT; kt++) {
        if (kt + 1 < KT) { issue(kt + 1, (kt + 1) & 1); CP_WAIT(1); }
        else             { CP_WAIT(0); }
        __syncthreads();

        uint32_t Asb = smem0 + ((kt & 1) * 2 * STAGE_F) * 4;
        uint32_t Bsb = Asb + STAGE_F * 4;

        #pragma unroll
        for (int ks = 0; ks < 4; ks++) {
            const int k0 = ks * 8;
            uint32_t af[4][4], bf[4][4];
            #pragma unroll
            for (int mi = 0; mi < 4; mi++)
                ldm_x4(af[mi], Asb + ((wm + mi * 16 + a_row) * SMSTRIDE + k0 + a_col) * 4);
            #pragma unroll
            for (int nj = 0; nj < 4; nj++)
                ldm_x4(bf[nj], Bsb + ((wn + nj * 16 + b_row) * SMSTRIDE + k0 + b_col) * 4);
            #pragma unroll
            for (int mi = 0; mi < 4; mi++)
                #pragma unroll
                for (int nj = 0; nj < 4; nj++) {
                    mma_tf32(acc[mi][2 * nj],     af[mi][0], af[mi][1], af[mi][2], af[mi][3],
                             bf[nj][0], bf[nj][1]);
                    mma_tf32(acc[mi][2 * nj + 1], af[mi][0], af[mi][1], af[mi][2], af[mi][3],
                             bf[nj][2], bf[nj][3]);
                }
        }
        __syncthreads();
    }

    const int fr = lane >> 2;
    const int fc = lane & 3;
    const int rowBase = blockIdx.y * 128 + wm;
    const int colBase = blockIdx.x * 128 + wn;
    #pragma unroll
    for (int mi = 0; mi < 4; mi++) {
        int r0 = rowBase + mi * 16 + fr;
        #pragma unroll
        for (int ni = 0; ni < 8; ni++) {
            int c0 = colBase + ni * 8 + fc * 2;
            epi_store<MODE, ROUND>(C, ldc, r0,     c0,     acc[mi][ni][0]);
            epi_store<MODE, ROUND>(C, ldc, r0,     c0 + 1, acc[mi][ni][1]);
            epi_store<MODE, ROUND>(C, ldc, r0 + 8, c0,     acc[mi][ni][2]);
            epi_store<MODE, ROUND>(C, ldc, r0 + 8, c0 + 1, acc[mi][ni][3]);
        }
    }
}

// -------------------- RoPE --------------------
__global__ void rope_kernel(float* __restrict__ buf) {
    int idx = blockIdx.x * blockDim.x + threadIdx.x;
    int i  = idx & 31;
    int m  = (idx >> 5) & 2047;
    int bh = idx >> 16;
    float* p = buf + ((long long)(bh * MM + m)) * DCAT + DH + 2 * i;
    double freq = exp(-(double)i / 32.0 * log(1.0e6));
    double ang  = (double)m * freq;
    double s, c;
    sincos(ang, &s, &c);
    float cf = (float)c, sf = (float)s;
    float x0 = p[0], x1 = p[1];
    p[0] = tf32r(x0 * cf - x1 * sf);
    p[1] = tf32r(x1 * cf + x0 * sf);
}

// -------------------- fused flash attention (unchanged from round 4) --------
#define FQ_STRIDE 196
#define FK_STRIDE 36
#define FV_STRIDE 132
#define FQ_F (128 * FQ_STRIDE)
#define FK_F (128 * FK_STRIDE)
#define FL_SMEM_BYTES ((FQ_F + 2 * FK_F + 128 * FV_STRIDE) * 4)   // 204800 B

__global__ void __launch_bounds__(256)
flash_kernel(const float* __restrict__ Q, const float* __restrict__ Kc,
             const float* __restrict__ Vt, float* __restrict__ Ctx)
{
    extern __shared__ float sm[];
    float* Qs = sm;
    float* Ks = sm + FQ_F;
    float* Vs = sm + FQ_F + 2 * FK_F;

    const int bh = blockIdx.y;
    const int m0 = blockIdx.x * 128;
    const int t = threadIdx.x;
    const int lane = t & 31;
    const int warp = t >> 5;
    const int fr = lane >> 2;
    const int fc = lane & 3;
    const int rw = warp * 16;

    const float* Qg = Q  + ((long long)bh * MM + m0) * DCAT;
    const float* Kg = Kc + (long long)bh * NN * DCAT;
    const float* Vg = Vt + (long long)bh * DH * NN;

    #pragma unroll
    for (int i = 0; i < 24; i++) {
        int id = t + 256 * i;
        int r = id / 48, c = (id % 48) * 4;
        cp16(&Qs[r * FQ_STRIDE + c], Qg + (long long)r * DCAT + c);
    }
    CP_COMMIT();

    auto issueK = [&](int n0, int ksub, int buf) {
        float* dst = Ks + buf * FK_F;
        #pragma unroll
        for (int i = 0; i < 4; i++) {
            int id = t + 256 * i;
            int r = id >> 3, c = (id & 7) * 4;
            cp16(&dst[r * FK_STRIDE + c],
                 Kg + (long long)(n0 + r) * DCAT + ksub * 32 + c);
        }
    };
    auto issueV = [&](int n0) {
        #pragma unroll
        for (int i = 0; i < 16; i++) {
            int id = t + 256 * i;
            int r = id >> 5, c = (id & 31) * 4;
            cp16(&Vs[r * FV_STRIDE + c], Vg + (long long)r * NN + n0 + c);
        }
    };

    issueK(0, 0, 0); issueV(0); CP_COMMIT();
    issueK(0, 1, 1); CP_COMMIT();

    float sacc[16][4], oacc[16][4];
    float mrun[2] = { -INFINITY, -INFINITY };
    float lrun[2] = { 0.f, 0.f };
    #pragma unroll
    for (int i = 0; i < 16; i++)
        #pragma unroll
        for (int q = 0; q < 4; q++) oacc[i][q] = 0.f;

    for (int chunk = 0; chunk < 16; chunk++) {
        const int n0 = chunk * 128;
        #pragma unroll
        for (int i = 0; i < 16; i++)
            #pragma unroll
            for (int q = 0; q < 4; q++) sacc[i][q] = 0.f;

        for (int ksub = 0; ksub < 6; ksub++) {
            if (ksub < 5) { CP_WAIT(1); } else { CP_WAIT(0); }
            __syncthreads();
            const float* Kb = Ks + (ksub & 1) * FK_F;
            #pragma unroll
            for (int kk = 0; kk < 4; kk++) {
                int qc = ksub * 32 + kk * 8 + fc;
                uint32_t a0 = __float_as_uint(Qs[(rw + fr) * FQ_STRIDE + qc]);
                uint32_t a1 = __float_as_uint(Qs[(rw + 8 + fr) * FQ_STRIDE + qc]);
                uint32_t a2 = __float_as_uint(Qs[(rw + fr) * FQ_STRIDE + qc + 4]);
                uint32_t a3 = __float_as_uint(Qs[(rw + 8 + fr) * FQ_STRIDE + qc + 4]);
                #pragma unroll
                for (int ni = 0; ni < 16; ni++) {
                    uint32_t b0 = __float_as_uint(Kb[(8 * ni + fr) * FK_STRIDE + kk * 8 + fc]);
                    uint32_t b1 = __float_as_uint(Kb[(8 * ni + fr) * FK_STRIDE + kk * 8 + fc + 4]);
                    mma_tf32(sacc[ni], a0, a1, a2, a3, b0, b1);
                }
            }
            __syncthreads();
            if (ksub + 2 < 6) { issueK(n0, ksub + 2, ksub & 1); CP_COMMIT(); }
        }

        #pragma unroll
        for (int i = 0; i < 16; i++)
            #pragma unroll
            for (int q = 0; q < 4; q++) sacc[i][q] *= SCALE_F;

        #pragma unroll
        for (int h = 0; h < 2; h++) {
            float cm = -INFINITY;
            #pragma unroll
            for (int ni = 0; ni < 16; ni++)
                cm = fmaxf(cm, fmaxf(sacc[ni][2 * h], sacc[ni][2 * h + 1]));
            cm = fmaxf(cm, __shfl_xor_sync(0xFFFFFFFF, cm, 1));
            cm = fmaxf(cm, __shfl_xor_sync(0xFFFFFFFF, cm, 2));
            float mnew = fmaxf(mrun[h], cm);
            float alpha = __expf(mrun[h] - mnew);
            mrun[h] = mnew;
            float rs = 0.f;
            #pragma unroll
            for (int ni = 0; ni < 16; ni++) {
                float p0 = __expf(sacc[ni][2 * h] - mnew);
                float p1 = __expf(sacc[ni][2 * h + 1] - mnew);
                rs += p0 + p1;
                sacc[ni][2 * h]     = tf32r(p0);
                sacc[ni][2 * h + 1] = tf32r(p1);
            }
            rs += __shfl_xor_sync(0xFFFFFFFF, rs, 1);
            rs += __shfl_xor_sync(0xFFFFFFFF, rs, 2);
            lrun[h] = lrun[h] * alpha + rs;
            #pragma unroll
            for (int ni = 0; ni < 16; ni++) {
                oacc[ni][2 * h]     *= alpha;
                oacc[ni][2 * h + 1] *= alpha;
            }
        }

        #pragma unroll
        for (int s = 0; s < 16; s++) {
            int srcA = (fr << 2) | (fc >> 1);
            int srcB = srcA + 2;
            float x0 = __shfl_sync(0xFFFFFFFF, sacc[s][0], srcA);
            float x1 = __shfl_sync(0xFFFFFFFF, sacc[s][1], srcA);
            float y0 = __shfl_sync(0xFFFFFFFF, sacc[s][0], srcB);
            float y1 = __shfl_sync(0xFFFFFFFF, sacc[s][1], srcB);
            float z0 = __shfl_sync(0xFFFFFFFF, sacc[s][2], srcA);
            float z1 = __shfl_sync(0xFFFFFFFF, sacc[s][3], srcA);
            float w0 = __shfl_sync(0xFFFFFFFF, sacc[s][2], srcB);
            float w1 = __shfl_sync(0xFFFFFFFF, sacc[s][3], srcB);
            bool odd = (fc & 1);
            uint32_t a0 = __float_as_uint(odd ? x1 : x0);
            uint32_t a2 = __float_as_uint(odd ? y1 : y0);
            uint32_t a1 = __float_as_uint(odd ? z1 : z0);
            uint32_t a3 = __float_as_uint(odd ? w1 : w0);
            #pragma unroll
            for (int nj = 0; nj < 16; nj++) {
                uint32_t b0 = __float_as_uint(Vs[(8 * nj + fr) * FV_STRIDE + 8 * s + fc]);
                uint32_t b1 = __float_as_uint(Vs[(8 * nj + fr) * FV_STRIDE + 8 * s + fc + 4]);
                mma_tf32(oacc[nj], a0, a1, a2, a3, b0, b1);
            }
        }
        __syncthreads();
        if (chunk + 1 < 16) {
            issueK(n0 + 128, 0, 0); issueV(n0 + 128); CP_COMMIT();
            issueK(n0 + 128, 1, 1); CP_COMMIT();
        }
    }

    const int b  = bh >> 4;
    const int hd = bh & 15;
    float inv0 = 1.f / lrun[0];
    float inv1 = 1.f / lrun[1];
    int r0 = m0 + rw + fr;
    #pragma unroll
    for (int nj = 0; nj < 16; nj++) {
        int d = hd * DH + nj * 8 + 2 * fc;
        long long base0 = ((long long)(b * MM + r0)) * (HH * DH) + d;
        long long base1 = ((long long)(b * MM + r0 + 8)) * (HH * DH) + d;
        Ctx[base0]     = tf32r(oacc[nj][0] * inv0);
        Ctx[base0 + 1] = tf32r(oacc[nj][1] * inv0);
        Ctx[base1]     = tf32r(oacc[nj][2] * inv1);
        Ctx[base1 + 1] = tf32r(oacc[nj][3] * inv1);
    }
}

// -------------------- launch --------------------
extern "C" void kernel_launch(void* const* d_in, const int* in_sizes, int n_in,
                              void* d_out, int out_size) {
    const float* query = (const float*)d_in[0];
    const float* kv    = (const float*)d_in[1];
    const float* W_QC  = (const float*)d_in[2];
    const float* W_KC  = (const float*)d_in[3];
    const float* W_QR  = (const float*)d_in[4];
    const float* W_KR  = (const float*)d_in[5];
    const float* W_V   = (const float*)d_in[6];
    const float* W_O   = (const float*)d_in[7];
    float* out = (float*)d_out;

    float *Qcat, *Kcat, *Vt, *Ctx;
    float *cq, *ckv, *wqc, *wkc, *wqr, *wkr, *wv, *wo;
    cudaGetSymbolAddress((void**)&Qcat, g_Qcat);
    cudaGetSymbolAddress((void**)&Kcat, g_Kcat);
    cudaGetSymbolAddress((void**)&Vt,   g_Vt);
    cudaGetSymbolAddress((void**)&Ctx,  g_Ctx);
    cudaGetSymbolAddress((void**)&cq,   g_cq);
    cudaGetSymbolAddress((void**)&ckv,  g_ckv);
    cudaGetSymbolAddress((void**)&wqc,  g_wqc);
    cudaGetSymbolAddress((void**)&wkc,  g_wkc);
    cudaGetSymbolAddress((void**)&wqr,  g_wqr);
    cudaGetSymbolAddress((void**)&wkr,  g_wkr);
    cudaGetSymbolAddress((void**)&wv,   g_wv);
    cudaGetSymbolAddress((void**)&wo,   g_wo);

    cudaFuncSetAttribute(mma_gemm<EPI_CATC, true>,  cudaFuncAttributeMaxDynamicSharedMemorySize, SMEM_BYTES);
    cudaFuncSetAttribute(mma_gemm<EPI_CATR, true>,  cudaFuncAttributeMaxDynamicSharedMemorySize, SMEM_BYTES);
    cudaFuncSetAttribute(mma_gemm<EPI_VT,   true>,  cudaFuncAttributeMaxDynamicSharedMemorySize, SMEM_BYTES);
    cudaFuncSetAttribute(mma_gemm<EPI_PLAIN,false>, cudaFuncAttributeMaxDynamicSharedMemorySize, SMEM_BYTES);
    cudaFuncSetAttribute(flash_kernel, cudaFuncAttributeMaxDynamicSharedMemorySize, FL_SMEM_BYTES);

    // ---- single merged tf32-round prepass ----
    ConvArgs ca;
    ca.src[0] = (const float4*)query; ca.dst[0] = (float4*)cq;  ca.n4[0] = BB*MM*DD/4;
    ca.src[1] = (const float4*)kv;    ca.dst[1] = (float4*)ckv; ca.n4[1] = BB*NN*DD/4;
    ca.src[2] = (const float4*)W_QC;  ca.dst[2] = (float4*)wqc; ca.n4[2] = HH*DH*DD/4;
    ca.src[3] = (const float4*)W_KC;  ca.dst[3] = (float4*)wkc; ca.n4[3] = HH*DH*DD/4;
    ca.src[4] = (const float4*)W_QR;  ca.dst[4] = (float4*)wqr; ca.n4[4] = HH*DR*DD/4;
    ca.src[5] = (const float4*)W_KR;  ca.dst[5] = (float4*)wkr; ca.n4[5] = HH*DR*DD/4;
    ca.src[6] = (const float4*)W_V;   ca.dst[6] = (float4*)wv;  ca.n4[6] = HH*DH*DD/4;
    ca.src[7] = (const float4*)W_O;   ca.dst[7] = (float4*)wo;  ca.n4[7] = DD*HH*DH/4;
    {
        int maxn4 = BB*MM*DD/4;
        conv8_kernel<<<dim3((maxn4 + 255) / 256, 8), 256>>>(ca);
    }

    dim3 gblk(128);

    // ---- projections ----
    mma_gemm<EPI_CATC, true><<<dim3(DD / 128, (BB * MM) / 128), gblk, SMEM_BYTES>>>(
        cq, DD, wqc, DD, Qcat, 0, DD);
    mma_gemm<EPI_CATR, true><<<dim3((HH * DR) / 128, (BB * MM) / 128), gblk, SMEM_BYTES>>>(
        cq, DD, wqr, DD, Qcat, 0, DD);
    mma_gemm<EPI_CATC, true><<<dim3(DD / 128, (BB * NN) / 128), gblk, SMEM_BYTES>>>(
        ckv, DD, wkc, DD, Kcat, 0, DD);
    mma_gemm<EPI_CATR, true><<<dim3((HH * DR) / 128, (BB * NN) / 128), gblk, SMEM_BYTES>>>(
        ckv, DD, wkr, DD, Kcat, 0, DD);
    mma_gemm<EPI_VT, true><<<dim3(DD / 128, (BB * NN) / 128), gblk, SMEM_BYTES>>>(
        ckv, DD, wv, DD, Vt, 0, DD);

    // ---- RoPE ----
    int rope_threads = BB * HH * MM * 32;
    rope_kernel<<<rope_threads / 256, 256>>>(Qcat);
    rope_kernel<<<rope_threads / 256, 256>>>(Kcat);

    // ---- fused flash attention ----
    flash_kernel<<<dim3(MM / 128, BB * HH), 256, FL_SMEM_BYTES>>>(Qcat, Kcat, Vt, Ctx);

    // ---- output projection ----
    mma_gemm<EPI_PLAIN, false><<<dim3(DD / 128, (BB * MM) / 128), gblk, SMEM_BYTES>>>(
        Ctx, HH * DH, wo, DD, out, DD, HH * DH);
}

// round 7
// speedup vs baseline: 3.7237x; 1.0353x over previous
#include <cuda_runtime.h>
#include <cuda_bf16.h>
#include <math.h>
#include <stdint.h>

// Problem constants
#define BB   2
#define HH   16
#define MM   2048
#define NN   2048
#define DD   2048
#define DH   128
#define DR   64
#define DCAT 192
#define SCALE_F 0.07216878364870323f   // 1/sqrt(192)

// -------------------- scratch --------------------
__device__ float g_Qcat[(long long)BB*HH*MM*DCAT];   // (B,H,M,192)
__device__ float g_Kcat[(long long)BB*HH*NN*DCAT];   // (B,H,N,192)
__device__ float g_Vt [(long long)BB*HH*DH*NN];      // (B,H,128,N)
__device__ float g_Ctx[(long long)BB*MM*HH*DH];      // (B*M, 2048)
__device__ float g_cq [(long long)BB*MM*DD];
__device__ float g_ckv[(long long)BB*NN*DD];
__device__ float g_wq [(long long)(HH*DH + HH*DR)*DD];          // QC(2048) ‖ QR(1024) rows
__device__ float g_wkv[(long long)(HH*DH + HH*DR + HH*DH)*DD];  // KC ‖ KR ‖ V rows
__device__ float g_wo [(long long)DD*HH*DH];

// -------------------- helpers --------------------
__device__ __forceinline__ float tf32r(float x) {
    uint32_t u;
    asm("cvt.rna.tf32.f32 %0, %1;" : "=r"(u) : "f"(x));
    return __uint_as_float(u);
}
__device__ __forceinline__ void cp16(void* smem, const void* g) {
    uint32_t s = (uint32_t)__cvta_generic_to_shared(smem);
    asm volatile("cp.async.cg.shared.global [%0], [%1], 16;" :: "r"(s), "l"(g));
}
#define CP_COMMIT() asm volatile("cp.async.commit_group;" ::: "memory")
#define CP_WAIT(n)  asm volatile("cp.async.wait_group %0;" :: "n"(n) : "memory")

__device__ __forceinline__ void mma_tf32(float acc[4],
        uint32_t a0, uint32_t a1, uint32_t a2, uint32_t a3,
        uint32_t b0, uint32_t b1) {
    asm volatile(
        "mma.sync.aligned.m16n8k8.row.col.f32.tf32.tf32.f32 "
        "{%0,%1,%2,%3},{%4,%5,%6,%7},{%8,%9},{%0,%1,%2,%3};"
        : "+f"(acc[0]), "+f"(acc[1]), "+f"(acc[2]), "+f"(acc[3])
        : "r"(a0), "r"(a1), "r"(a2), "r"(a3), "r"(b0), "r"(b1));
}

__device__ __forceinline__ void ldm_x4(uint32_t r[4], uint32_t saddr) {
    asm volatile("ldmatrix.sync.aligned.m8n8.x4.shared.b16 {%0,%1,%2,%3}, [%4];"
                 : "=r"(r[0]), "=r"(r[1]), "=r"(r[2]), "=r"(r[3]) : "r"(saddr));
}

// -------------------- merged input conversion (1 launch) --------------------
struct ConvArgs {
    const float4* src[8];
    float4*       dst[8];
    int           n4[8];
};
__global__ void conv8_kernel(ConvArgs a) {
    int seg = blockIdx.y;
    int i = blockIdx.x * blockDim.x + threadIdx.x;
    if (i < a.n4[seg]) {
        float4 v = a.src[seg][i];
        v.x = tf32r(v.x); v.y = tf32r(v.y); v.z = tf32r(v.z); v.w = tf32r(v.w);
        a.dst[seg][i] = v;
    }
}

// -------------------- epilogue modes --------------------
enum { EPI_PLAIN = 0, EPI_Q = 1, EPI_KV = 2 };

template<int MODE, bool ROUND>
__device__ __forceinline__ void epi_store(float* __restrict__ C, float* __restrict__ C2,
                                          int ldc, int r, int c, float v) {
    if (ROUND) v = tf32r(v);
    if (MODE == EPI_PLAIN) {
        C[(long long)r * ldc + c] = v;
    } else if (MODE == EPI_Q) {
        int b = r >> 11, m = r & 2047;
        if (c < 2048) {
            int h = c >> 7, d = c & 127;
            C[((long long)((b * HH + h) * MM + m)) * DCAT + d] = v;
        } else {
            int c2 = c - 2048, h = c2 >> 6, d = c2 & 63;
            C[((long long)((b * HH + h) * MM + m)) * DCAT + DH + d] = v;
        }
    } else { // EPI_KV: C = Kcat, C2 = Vt
        int b = r >> 11, n = r & 2047;
        if (c < 2048) {
            int h = c >> 7, d = c & 127;
            C[((long long)((b * HH + h) * NN + n)) * DCAT + d] = v;
        } else if (c < 3072) {
            int c2 = c - 2048, h = c2 >> 6, d = c2 & 63;
            C[((long long)((b * HH + h) * NN + n)) * DCAT + DH + d] = v;
        } else {
            int c2 = c - 3072, h = c2 >> 7, d = c2 & 127;
            C2[((long long)((b * HH + h) * DH + d)) * NN + n] = v;
        }
    }
}

// -------------------- tf32 mma.sync GEMM: C = A * B^T --------------------
// 128x128 CTA tile, 4 warps (2x2), warp tile 64x64, BK=32, double-buffered.
#define SMSTRIDE 36
#define STAGE_F  (128 * SMSTRIDE)
#define SMEM_BYTES (4 * STAGE_F * 4)        // 73728 B

template<int MODE, bool ROUND>
__global__ void __launch_bounds__(128, 3)
mma_gemm(const float* __restrict__ A, int lda,
         const float* __restrict__ Bm, int ldb,
         float* __restrict__ C, float* __restrict__ C2, int ldc, int K)
{
    extern __shared__ float sm[];
    const float* Ab = A  + (long long)blockIdx.y * 128 * lda;
    const float* Bb = Bm + (long long)blockIdx.x * 128 * ldb;

    const int t = threadIdx.x;
    const int lane = t & 31;
    const int warp = t >> 5;
    const int wm = (warp & 1) * 64;
    const int wn = (warp >> 1) * 64;

    const int lrow = lane & 7;
    const int lsel = lane >> 3;
    const int a_row = lrow + (lsel & 1) * 8;
    const int a_col = (lsel >> 1) * 4;
    const int b_row = lrow + (lsel >> 1) * 8;
    const int b_col = (lsel & 1) * 4;

    const uint32_t smem0 = (uint32_t)__cvta_generic_to_shared(sm);

    float acc[4][8][4];
    #pragma unroll
    for (int i = 0; i < 4; i++)
        #pragma unroll
        for (int j = 0; j < 8; j++)
            #pragma unroll
            for (int q = 0; q < 4; q++) acc[i][j][q] = 0.f;

    const int KT = K >> 5;

    auto issue = [&](int kt, int buf) {
        float* Asb = sm + buf * 2 * STAGE_F;
        float* Bsb = Asb + STAGE_F;
        const float* Ag = Ab + kt * 32;
        const float* Bg = Bb + kt * 32;
        #pragma unroll
        for (int i = 0; i < 8; i++) {
            int id = t + 128 * i;
            int row = id >> 3, cc = (id & 7) * 4;
            cp16(&Asb[row * SMSTRIDE + cc], Ag + (long long)row * lda + cc);
            cp16(&Bsb[row * SMSTRIDE + cc], Bg + (long long)row * ldb + cc);
        }
        CP_COMMIT();
    };

    issue(0, 0);

    for (int kt = 0; kt < KT; kt++) {
        if (kt + 1 < KT) { issue(kt + 1, (kt + 1) & 1); CP_WAIT(1); }
        else             { CP_WAIT(0); }
        __syncthreads();

        uint32_t Asb = smem0 + ((kt & 1) * 2 * STAGE_F) * 4;
        uint32_t Bsb = Asb + STAGE_F * 4;

        #pragma unroll
        for (int ks = 0; ks < 4; ks++) {
            const int k0 = ks * 8;
            uint32_t af[4][4], bf[4][4];
            #pragma unroll
            for (int mi = 0; mi < 4; mi++)
                ldm_x4(af[mi], Asb + ((wm + mi * 16 + a_row) * SMSTRIDE + k0 + a_col) * 4);
            #pragma unroll
            for (int nj = 0; nj < 4; nj++)
                ldm_x4(bf[nj], Bsb + ((wn + nj * 16 + b_row) * SMSTRIDE + k0 + b_col) * 4);
            #pragma unroll
            for (int mi = 0; mi < 4; mi++)
                #pragma unroll
                for (int nj = 0; nj < 4; nj++) {
                    mma_tf32(acc[mi][2 * nj],     af[mi][0], af[mi][1], af[mi][2], af[mi][3],
                             bf[nj][0], bf[nj][1]);
                    mma_tf32(acc[mi][2 * nj + 1], af[mi][0], af[mi][1], af[mi][2], af[mi][3],
                             bf[nj][2], bf[nj][3]);
                }
        }
        __syncthreads();
    }

    const int fr = lane >> 2;
    const int fc = lane & 3;
    const int rowBase = blockIdx.y * 128 + wm;
    const int colBase = blockIdx.x * 128 + wn;
    #pragma unroll
    for (int mi = 0; mi < 4; mi++) {
        int r0 = rowBase + mi * 16 + fr;
        #pragma unroll
        for (int ni = 0; ni < 8; ni++) {
            int c0 = colBase + ni * 8 + fc * 2;
            epi_store<MODE, ROUND>(C, C2, ldc, r0,     c0,     acc[mi][ni][0]);
            epi_store<MODE, ROUND>(C, C2, ldc, r0,     c0 + 1, acc[mi][ni][1]);
            epi_store<MODE, ROUND>(C, C2, ldc, r0 + 8, c0,     acc[mi][ni][2]);
            epi_store<MODE, ROUND>(C, C2, ldc, r0 + 8, c0 + 1, acc[mi][ni][3]);
        }
    }
}

// -------------------- RoPE --------------------
__global__ void rope_kernel(float* __restrict__ buf) {
    int idx = blockIdx.x * blockDim.x + threadIdx.x;
    int i  = idx & 31;
    int m  = (idx >> 5) & 2047;
    int bh = idx >> 16;
    float* p = buf + ((long long)(bh * MM + m)) * DCAT + DH + 2 * i;
    double freq = exp(-(double)i / 32.0 * log(1.0e6));
    double ang  = (double)m * freq;
    double s, c;
    sincos(ang, &s, &c);
    float cf = (float)c, sf = (float)s;
    float x0 = p[0], x1 = p[1];
    p[0] = tf32r(x0 * cf - x1 * sf);
    p[1] = tf32r(x1 * cf + x0 * sf);
}

// -------------------- fused flash attention --------------------
#define FQ_STRIDE 196
#define FK_STRIDE 36
#define FV_STRIDE 132
#define FQ_F (128 * FQ_STRIDE)
#define FK_F (128 * FK_STRIDE)
#define FL_SMEM_BYTES ((FQ_F + 2 * FK_F + 128 * FV_STRIDE) * 4)   // 204800 B

__global__ void __launch_bounds__(256)
flash_kernel(const float* __restrict__ Q, const float* __restrict__ Kc,
             const float* __restrict__ Vt, float* __restrict__ Ctx)
{
    extern __shared__ float sm[];
    float* Qs = sm;
    float* Ks = sm + FQ_F;
    float* Vs = sm + FQ_F + 2 * FK_F;

    const int bh = blockIdx.y;
    const int m0 = blockIdx.x * 128;
    const int t = threadIdx.x;
    const int lane = t & 31;
    const int warp = t >> 5;
    const int fr = lane >> 2;
    const int fc = lane & 3;
    const int rw = warp * 16;

    // ldmatrix lane addressing (same recipe as mma_gemm, validated)
    const int lrow = lane & 7;
    const int lsel = lane >> 3;
    const int a_row = lrow + (lsel & 1) * 8;
    const int a_col = (lsel >> 1) * 4;
    const int b_row = lrow + (lsel >> 1) * 8;
    const int b_col = (lsel & 1) * 4;

    const uint32_t qs_b = (uint32_t)__cvta_generic_to_shared(Qs);
    const uint32_t ks_b = (uint32_t)__cvta_generic_to_shared(Ks);
    const uint32_t vs_b = (uint32_t)__cvta_generic_to_shared(Vs);

    const float* Qg = Q  + ((long long)bh * MM + m0) * DCAT;
    const float* Kg = Kc + (long long)bh * NN * DCAT;
    const float* Vg = Vt + (long long)bh * DH * NN;

    #pragma unroll
    for (int i = 0; i < 24; i++) {
        int id = t + 256 * i;
        int r = id / 48, c = (id % 48) * 4;
        cp16(&Qs[r * FQ_STRIDE + c], Qg + (long long)r * DCAT + c);
    }
    CP_COMMIT();

    auto issueK = [&](int n0, int ksub, int buf) {
        float* dst = Ks + buf * FK_F;
        #pragma unroll
        for (int i = 0; i < 4; i++) {
            int id = t + 256 * i;
            int r = id >> 3, c = (id & 7) * 4;
            cp16(&dst[r * FK_STRIDE + c],
                 Kg + (long long)(n0 + r) * DCAT + ksub * 32 + c);
        }
    };
    auto issueV = [&](int n0) {
        #pragma unroll
        for (int i = 0; i < 16; i++) {
            int id = t + 256 * i;
            int r = id >> 5, c = (id & 31) * 4;
            cp16(&Vs[r * FV_STRIDE + c], Vg + (long long)r * NN + n0 + c);
        }
    };

    issueK(0, 0, 0); issueV(0); CP_COMMIT();
    issueK(0, 1, 1); CP_COMMIT();

    float sacc[16][4], oacc[16][4];
    float mrun[2] = { -INFINITY, -INFINITY };
    float lrun[2] = { 0.f, 0.f };
    #pragma unroll
    for (int i = 0; i < 16; i++)
        #pragma unroll
        for (int q = 0; q < 4; q++) oacc[i][q] = 0.f;

    for (int chunk = 0; chunk < 16; chunk++) {
        const int n0 = chunk * 128;
        #pragma unroll
        for (int i = 0; i < 16; i++)
            #pragma unroll
            for (int q = 0; q < 4; q++) sacc[i][q] = 0.f;

        // ---- S = Q @ K^T via ldmatrix fragments ----
        for (int ksub = 0; ksub < 6; ksub++) {
            if (ksub < 5) { CP_WAIT(1); } else { CP_WAIT(0); }
            __syncthreads();
            uint32_t Kb = ks_b + ((ksub & 1) * FK_F) * 4;
            #pragma unroll
            for (int kk = 0; kk < 4; kk++) {
                int qc = ksub * 32 + kk * 8;
                uint32_t af[4];
                ldm_x4(af, qs_b + ((rw + a_row) * FQ_STRIDE + qc + a_col) * 4);
                #pragma unroll
                for (int np = 0; np < 8; np++) {
                    uint32_t bf[4];
                    ldm_x4(bf, Kb + ((16 * np + b_row) * FK_STRIDE + kk * 8 + b_col) * 4);
                    mma_tf32(sacc[2 * np],     af[0], af[1], af[2], af[3], bf[0], bf[1]);
                    mma_tf32(sacc[2 * np + 1], af[0], af[1], af[2], af[3], bf[2], bf[3]);
                }
            }
            __syncthreads();
            if (ksub + 2 < 6) { issueK(n0, ksub + 2, ksub & 1); CP_COMMIT(); }
        }

        // ---- online softmax ----
        #pragma unroll
        for (int i = 0; i < 16; i++)
            #pragma unroll
            for (int q = 0; q < 4; q++) sacc[i][q] *= SCALE_F;

        #pragma unroll
        for (int h = 0; h < 2; h++) {
            float cm = -INFINITY;
            #pragma unroll
            for (int ni = 0; ni < 16; ni++)
                cm = fmaxf(cm, fmaxf(sacc[ni][2 * h], sacc[ni][2 * h + 1]));
            cm = fmaxf(cm, __shfl_xor_sync(0xFFFFFFFF, cm, 1));
            cm = fmaxf(cm, __shfl_xor_sync(0xFFFFFFFF, cm, 2));
            float mnew = fmaxf(mrun[h], cm);
            float alpha = __expf(mrun[h] - mnew);
            mrun[h] = mnew;
            float rs = 0.f;
            #pragma unroll
            for (int ni = 0; ni < 16; ni++) {
                float p0 = __expf(sacc[ni][2 * h] - mnew);
                float p1 = __expf(sacc[ni][2 * h + 1] - mnew);
                rs += p0 + p1;
                sacc[ni][2 * h]     = tf32r(p0);
                sacc[ni][2 * h + 1] = tf32r(p1);
            }
            rs += __shfl_xor_sync(0xFFFFFFFF, rs, 1);
            rs += __shfl_xor_sync(0xFFFFFFFF, rs, 2);
            lrun[h] = lrun[h] * alpha + rs;
            #pragma unroll
            for (int ni = 0; ni < 16; ni++) {
                oacc[ni][2 * h]     *= alpha;
                oacc[ni][2 * h + 1] *= alpha;
            }
        }

        // ---- O += P @ V (A via shuffles, B via ldmatrix) ----
        #pragma unroll
        for (int s = 0; s < 16; s++) {
            int srcA = (fr << 2) | (fc >> 1);
            int srcB = srcA + 2;
            float x0 = __shfl_sync(0xFFFFFFFF, sacc[s][0], srcA);
            float x1 = __shfl_sync(0xFFFFFFFF, sacc[s][1], srcA);
            float y0 = __shfl_sync(0xFFFFFFFF, sacc[s][0], srcB);
            float y1 = __shfl_sync(0xFFFFFFFF, sacc[s][1], srcB);
            float z0 = __shfl_sync(0xFFFFFFFF, sacc[s][2], srcA);
            float z1 = __shfl_sync(0xFFFFFFFF, sacc[s][3], srcA);
            float w0 = __shfl_sync(0xFFFFFFFF, sacc[s][2], srcB);
            float w1 = __shfl_sync(0xFFFFFFFF, sacc[s][3], srcB);
            bool odd = (fc & 1);
            uint32_t a0 = __float_as_uint(odd ? x1 : x0);
            uint32_t a2 = __float_as_uint(odd ? y1 : y0);
            uint32_t a1 = __float_as_uint(odd ? z1 : z0);
            uint32_t a3 = __float_as_uint(odd ? w1 : w0);
            #pragma unroll
            for (int np = 0; np < 8; np++) {
                uint32_t bf[4];
                ldm_x4(bf, vs_b + ((16 * np + b_row) * FV_STRIDE + 8 * s + b_col) * 4);
                mma_tf32(oacc[2 * np],     a0, a1, a2, a3, bf[0], bf[1]);
                mma_tf32(oacc[2 * np + 1], a0, a1, a2, a3, bf[2], bf[3]);
            }
        }
        __syncthreads();
        if (chunk + 1 < 16) {
            issueK(n0 + 128, 0, 0); issueV(n0 + 128); CP_COMMIT();
            issueK(n0 + 128, 1, 1); CP_COMMIT();
        }
    }

    const int b  = bh >> 4;
    const int hd = bh & 15;
    float inv0 = 1.f / lrun[0];
    float inv1 = 1.f / lrun[1];
    int r0 = m0 + rw + fr;
    #pragma unroll
    for (int nj = 0; nj < 16; nj++) {
        int d = hd * DH + nj * 8 + 2 * fc;
        long long base0 = ((long long)(b * MM + r0)) * (HH * DH) + d;
        long long base1 = ((long long)(b * MM + r0 + 8)) * (HH * DH) + d;
        Ctx[base0]     = tf32r(oacc[nj][0] * inv0);
        Ctx[base0 + 1] = tf32r(oacc[nj][1] * inv0);
        Ctx[base1]     = tf32r(oacc[nj][2] * inv1);
        Ctx[base1 + 1] = tf32r(oacc[nj][3] * inv1);
    }
}

// -------------------- launch --------------------
extern "C" void kernel_launch(void* const* d_in, const int* in_sizes, int n_in,
                              void* d_out, int out_size) {
    const float* query = (const float*)d_in[0];
    const float* kv    = (const float*)d_in[1];
    const float* W_QC  = (const float*)d_in[2];
    const float* W_KC  = (const float*)d_in[3];
    const float* W_QR  = (const float*)d_in[4];
    const float* W_KR  = (const float*)d_in[5];
    const float* W_V   = (const float*)d_in[6];
    const float* W_O   = (const float*)d_in[7];
    float* out = (float*)d_out;

    float *Qcat, *Kcat, *Vt, *Ctx, *cq, *ckv, *wq, *wkv, *wo;
    cudaGetSymbolAddress((void**)&Qcat, g_Qcat);
    cudaGetSymbolAddress((void**)&Kcat, g_Kcat);
    cudaGetSymbolAddress((void**)&Vt,   g_Vt);
    cudaGetSymbolAddress((void**)&Ctx,  g_Ctx);
    cudaGetSymbolAddress((void**)&cq,   g_cq);
    cudaGetSymbolAddress((void**)&ckv,  g_ckv);
    cudaGetSymbolAddress((void**)&wq,   g_wq);
    cudaGetSymbolAddress((void**)&wkv,  g_wkv);
    cudaGetSymbolAddress((void**)&wo,   g_wo);

    cudaFuncSetAttribute(mma_gemm<EPI_Q,    true>,  cudaFuncAttributeMaxDynamicSharedMemorySize, SMEM_BYTES);
    cudaFuncSetAttribute(mma_gemm<EPI_KV,   true>,  cudaFuncAttributeMaxDynamicSharedMemorySize, SMEM_BYTES);
    cudaFuncSetAttribute(mma_gemm<EPI_PLAIN,false>, cudaFuncAttributeMaxDynamicSharedMemorySize, SMEM_BYTES);
    cudaFuncSetAttribute(flash_kernel, cudaFuncAttributeMaxDynamicSharedMemorySize, FL_SMEM_BYTES);

    // ---- single merged tf32-round prepass (weights land stacked) ----
    ConvArgs ca;
    ca.src[0] = (const float4*)query; ca.dst[0] = (float4*)cq;   ca.n4[0] = BB*MM*DD/4;
    ca.src[1] = (const float4*)kv;    ca.dst[1] = (float4*)ckv;  ca.n4[1] = BB*NN*DD/4;
    ca.src[2] = (const float4*)W_QC;  ca.dst[2] = (float4*)wq;                          ca.n4[2] = HH*DH*DD/4;
    ca.src[3] = (const float4*)W_QR;  ca.dst[3] = (float4*)(wq + (long long)HH*DH*DD);  ca.n4[3] = HH*DR*DD/4;
    ca.src[4] = (const float4*)W_KC;  ca.dst[4] = (float4*)wkv;                         ca.n4[4] = HH*DH*DD/4;
    ca.src[5] = (const float4*)W_KR;  ca.dst[5] = (float4*)(wkv + (long long)HH*DH*DD); ca.n4[5] = HH*DR*DD/4;
    ca.src[6] = (const float4*)W_V;   ca.dst[6] = (float4*)(wkv + (long long)(HH*DH + HH*DR)*DD); ca.n4[6] = HH*DH*DD/4;
    ca.src[7] = (const float4*)W_O;   ca.dst[7] = (float4*)wo;   ca.n4[7] = DD*HH*DH/4;
    {
        int maxn4 = BB*MM*DD/4;
        conv8_kernel<<<dim3((maxn4 + 255) / 256, 8), 256>>>(ca);
    }

    dim3 gblk(128);

    // ---- merged projections ----
    // Q-side: cols 0..3071 (QC 2048 ‖ QR 1024)
    mma_gemm<EPI_Q, true><<<dim3(3072 / 128, (BB * MM) / 128), gblk, SMEM_BYTES>>>(
        cq, DD, wq, DD, Qcat, nullptr, 0, DD);
    // KV-side: cols 0..5119 (KC 2048 ‖ KR 1024 ‖ V 2048)
    mma_gemm<EPI_KV, true><<<dim3(5120 / 128, (BB * NN) / 128), gblk, SMEM_BYTES>>>(
        ckv, DD, wkv, DD, Kcat, Vt, 0, DD);

    // ---- RoPE ----
    int rope_threads = BB * HH * MM * 32;
    rope_kernel<<<rope_threads / 256, 256>>>(Qcat);
    rope_kernel<<<rope_threads / 256, 256>>>(Kcat);

    // ---- fused flash attention ----
    flash_kernel<<<dim3(MM / 128, BB * HH), 256, FL_SMEM_BYTES>>>(Qcat, Kcat, Vt, Ctx);

    // ---- output projection ----
    mma_gemm<EPI_PLAIN, false><<<dim3(DD / 128, (BB * MM) / 128), gblk, SMEM_BYTES>>>(
        Ctx, HH * DH, wo, DD, out, nullptr, DD, HH * DH);
}

// round 8
// speedup vs baseline: 4.8908x; 1.3134x over previous
#include <cuda_runtime.h>
#include <cuda_bf16.h>
#include <math.h>
#include <stdint.h>

// Problem constants
#define BB   2
#define HH   16
#define MM   2048
#define NN   2048
#define DD   2048
#define DH   128
#define DR   64
#define DCAT 192
#define SCALE_F 0.07216878364870323f   // 1/sqrt(192)

// -------------------- scratch --------------------
__device__ float g_Qcat[(long long)BB*HH*MM*DCAT];   // (B,H,M,192)
__device__ float g_Kcat[(long long)BB*HH*NN*DCAT];   // (B,H,N,192)
__device__ float g_Vt [(long long)BB*HH*DH*NN];      // (B,H,128,N)
__device__ float g_Ctx[(long long)BB*MM*HH*DH];      // (B*M, 2048)
__device__ float g_cq [(long long)BB*MM*DD];
__device__ float g_ckv[(long long)BB*NN*DD];
__device__ float g_wq [(long long)(HH*DH + HH*DR)*DD];          // QC(2048) ‖ QR(1024) rows
__device__ float g_wkv[(long long)(HH*DH + HH*DR + HH*DH)*DD];  // KC ‖ KR ‖ V rows
__device__ float g_wo [(long long)DD*HH*DH];
__device__ float2 g_rope[MM * 32];                   // (cos,sin) per (m, i)

// -------------------- helpers --------------------
__device__ __forceinline__ float tf32r(float x) {
    uint32_t u;
    asm("cvt.rna.tf32.f32 %0, %1;" : "=r"(u) : "f"(x));
    return __uint_as_float(u);
}
__device__ __forceinline__ void cp16(void* smem, const void* g) {
    uint32_t s = (uint32_t)__cvta_generic_to_shared(smem);
    asm volatile("cp.async.cg.shared.global [%0], [%1], 16;" :: "r"(s), "l"(g));
}
#define CP_COMMIT() asm volatile("cp.async.commit_group;" ::: "memory")
#define CP_WAIT(n)  asm volatile("cp.async.wait_group %0;" :: "n"(n) : "memory")

__device__ __forceinline__ void mma_tf32(float acc[4],
        uint32_t a0, uint32_t a1, uint32_t a2, uint32_t a3,
        uint32_t b0, uint32_t b1) {
    asm volatile(
        "mma.sync.aligned.m16n8k8.row.col.f32.tf32.tf32.f32 "
        "{%0,%1,%2,%3},{%4,%5,%6,%7},{%8,%9},{%0,%1,%2,%3};"
        : "+f"(acc[0]), "+f"(acc[1]), "+f"(acc[2]), "+f"(acc[3])
        : "r"(a0), "r"(a1), "r"(a2), "r"(a3), "r"(b0), "r"(b1));
}

__device__ __forceinline__ void ldm_x4(uint32_t r[4], uint32_t saddr) {
    asm volatile("ldmatrix.sync.aligned.m8n8.x4.shared.b16 {%0,%1,%2,%3}, [%4];"
                 : "=r"(r[0]), "=r"(r[1]), "=r"(r[2]), "=r"(r[3]) : "r"(saddr));
}

// -------------------- rope table (65536 double sincos, once) --------------
__global__ void rope_table_kernel() {
    int idx = blockIdx.x * blockDim.x + threadIdx.x;   // MM*32
    int i = idx & 31;
    int m = idx >> 5;
    double freq = exp(-(double)i / 32.0 * log(1.0e6));
    double ang  = (double)m * freq;
    double s, c;
    sincos(ang, &s, &c);
    g_rope[idx] = make_float2((float)c, (float)s);
}

// -------------------- merged input conversion (1 launch) --------------------
struct ConvArgs {
    const float4* src[8];
    float4*       dst[8];
    int           n4[8];
};
__global__ void conv8_kernel(ConvArgs a) {
    int seg = blockIdx.y;
    int i = blockIdx.x * blockDim.x + threadIdx.x;
    if (i < a.n4[seg]) {
        float4 v = a.src[seg][i];
        v.x = tf32r(v.x); v.y = tf32r(v.y); v.z = tf32r(v.z); v.w = tf32r(v.w);
        a.dst[seg][i] = v;
    }
}

// -------------------- epilogue modes --------------------
enum { EPI_PLAIN = 0, EPI_Q = 1, EPI_KV = 2 };

// Stores an adjacent even/odd column pair (c, c+1); applies RoPE for R-range.
template<int MODE, bool ROUND>
__device__ __forceinline__ void epi_store2(float* __restrict__ C, float* __restrict__ C2,
                                           int ldc, int r, int c, float v0, float v1) {
    if (MODE == EPI_PLAIN) {
        C[(long long)r * ldc + c]     = v0;
        C[(long long)r * ldc + c + 1] = v1;
        return;
    }
    int b = r >> 11, sr = r & 2047;   // sr = m or n
    if (c < 2048) {
        int h = c >> 7, d = c & 127;
        float* p = C + ((long long)((b * HH + h) * (MODE == EPI_Q ? MM : NN) + sr)) * DCAT + d;
        p[0] = tf32r(v0); p[1] = tf32r(v1);
    } else if (c < 3072) {
        int c2 = c - 2048, h = c2 >> 6, d = c2 & 63;
        float2 cs = g_rope[sr * 32 + (d >> 1)];
        float o0 = v0 * cs.x - v1 * cs.y;
        float o1 = v1 * cs.x + v0 * cs.y;
        float* p = C + ((long long)((b * HH + h) * (MODE == EPI_Q ? MM : NN) + sr)) * DCAT + DH + d;
        p[0] = tf32r(o0); p[1] = tf32r(o1);
    } else {   // EPI_KV only: V -> Vt[b,h,d,n]
        int c2 = c - 3072, h = c2 >> 7, d = c2 & 127;
        float* p = C2 + ((long long)((b * HH + h) * DH + d)) * NN + sr;
        p[0]  = tf32r(v0);
        p[NN] = tf32r(v1);
    }
}

// -------------------- tf32 mma.sync GEMM: C = A * B^T --------------------
// 128x128 CTA tile, 4 warps (2x2), warp tile 64x64, BK=32, double-buffered.
#define SMSTRIDE 36
#define STAGE_F  (128 * SMSTRIDE)
#define SMEM_BYTES (4 * STAGE_F * 4)        // 73728 B

template<int MODE, bool ROUND>
__global__ void __launch_bounds__(128, 3)
mma_gemm(const float* __restrict__ A, int lda,
         const float* __restrict__ Bm, int ldb,
         float* __restrict__ C, float* __restrict__ C2, int ldc, int K)
{
    extern __shared__ float sm[];
    const float* Ab = A  + (long long)blockIdx.y * 128 * lda;
    const float* Bb = Bm + (long long)blockIdx.x * 128 * ldb;

    const int t = threadIdx.x;
    const int lane = t & 31;
    const int warp = t >> 5;
    const int wm = (warp & 1) * 64;
    const int wn = (warp >> 1) * 64;

    const int lrow = lane & 7;
    const int lsel = lane >> 3;
    const int a_row = lrow + (lsel & 1) * 8;
    const int a_col = (lsel >> 1) * 4;
    const int b_row = lrow + (lsel >> 1) * 8;
    const int b_col = (lsel & 1) * 4;

    const uint32_t smem0 = (uint32_t)__cvta_generic_to_shared(sm);

    float acc[4][8][4];
    #pragma unroll
    for (int i = 0; i < 4; i++)
        #pragma unroll
        for (int j = 0; j < 8; j++)
            #pragma unroll
            for (int q = 0; q < 4; q++) acc[i][j][q] = 0.f;

    const int KT = K >> 5;

    auto issue = [&](int kt, int buf) {
        float* Asb = sm + buf * 2 * STAGE_F;
        float* Bsb = Asb + STAGE_F;
        const float* Ag = Ab + kt * 32;
        const float* Bg = Bb + kt * 32;
        #pragma unroll
        for (int i = 0; i < 8; i++) {
            int id = t + 128 * i;
            int row = id >> 3, cc = (id & 7) * 4;
            cp16(&Asb[row * SMSTRIDE + cc], Ag + (long long)row * lda + cc);
            cp16(&Bsb[row * SMSTRIDE + cc], Bg + (long long)row * ldb + cc);
        }
        CP_COMMIT();
    };

    issue(0, 0);

    for (int kt = 0; kt < KT; kt++) {
        if (kt + 1 < KT) { issue(kt + 1, (kt + 1) & 1); CP_WAIT(1); }
        else             { CP_WAIT(0); }
        __syncthreads();

        uint32_t Asb = smem0 + ((kt & 1) * 2 * STAGE_F) * 4;
        uint32_t Bsb = Asb + STAGE_F * 4;

        #pragma unroll
        for (int ks = 0; ks < 4; ks++) {
            const int k0 = ks * 8;
            uint32_t af[4][4], bf[4][4];
            #pragma unroll
            for (int mi = 0; mi < 4; mi++)
                ldm_x4(af[mi], Asb + ((wm + mi * 16 + a_row) * SMSTRIDE + k0 + a_col) * 4);
            #pragma unroll
            for (int nj = 0; nj < 4; nj++)
                ldm_x4(bf[nj], Bsb + ((wn + nj * 16 + b_row) * SMSTRIDE + k0 + b_col) * 4);
            #pragma unroll
            for (int mi = 0; mi < 4; mi++)
                #pragma unroll
                for (int nj = 0; nj < 4; nj++) {
                    mma_tf32(acc[mi][2 * nj],     af[mi][0], af[mi][1], af[mi][2], af[mi][3],
                             bf[nj][0], bf[nj][1]);
                    mma_tf32(acc[mi][2 * nj + 1], af[mi][0], af[mi][1], af[mi][2], af[mi][3],
                             bf[nj][2], bf[nj][3]);
                }
        }
        __syncthreads();
    }

    const int fr = lane >> 2;
    const int fc = lane & 3;
    const int rowBase = blockIdx.y * 128 + wm;
    const int colBase = blockIdx.x * 128 + wn;
    #pragma unroll
    for (int mi = 0; mi < 4; mi++) {
        int r0 = rowBase + mi * 16 + fr;
        #pragma unroll
        for (int ni = 0; ni < 8; ni++) {
            int c0 = colBase + ni * 8 + fc * 2;
            epi_store2<MODE, ROUND>(C, C2, ldc, r0,     c0, acc[mi][ni][0], acc[mi][ni][1]);
            epi_store2<MODE, ROUND>(C, C2, ldc, r0 + 8, c0, acc[mi][ni][2], acc[mi][ni][3]);
        }
    }
}

// -------------------- fused flash attention --------------------
#define FQ_STRIDE 196
#define FK_STRIDE 36
#define FV_STRIDE 132
#define FQ_F (128 * FQ_STRIDE)
#define FK_F (128 * FK_STRIDE)
#define FL_SMEM_BYTES ((FQ_F + 2 * FK_F + 128 * FV_STRIDE) * 4)   // 204800 B

__global__ void __launch_bounds__(256)
flash_kernel(const float* __restrict__ Q, const float* __restrict__ Kc,
             const float* __restrict__ Vt, float* __restrict__ Ctx)
{
    extern __shared__ float sm[];
    float* Qs = sm;
    float* Ks = sm + FQ_F;
    float* Vs = sm + FQ_F + 2 * FK_F;

    const int bh = blockIdx.y;
    const int m0 = blockIdx.x * 128;
    const int t = threadIdx.x;
    const int lane = t & 31;
    const int warp = t >> 5;
    const int fr = lane >> 2;
    const int fc = lane & 3;
    const int rw = warp * 16;

    const int lrow = lane & 7;
    const int lsel = lane >> 3;
    const int a_row = lrow + (lsel & 1) * 8;
    const int a_col = (lsel >> 1) * 4;
    const int b_row = lrow + (lsel >> 1) * 8;
    const int b_col = (lsel & 1) * 4;

    const uint32_t qs_b = (uint32_t)__cvta_generic_to_shared(Qs);
    const uint32_t ks_b = (uint32_t)__cvta_generic_to_shared(Ks);
    const uint32_t vs_b = (uint32_t)__cvta_generic_to_shared(Vs);

    const float* Qg = Q  + ((long long)bh * MM + m0) * DCAT;
    const float* Kg = Kc + (long long)bh * NN * DCAT;
    const float* Vg = Vt + (long long)bh * DH * NN;

    #pragma unroll
    for (int i = 0; i < 24; i++) {
        int id = t + 256 * i;
        int r = id / 48, c = (id % 48) * 4;
        cp16(&Qs[r * FQ_STRIDE + c], Qg + (long long)r * DCAT + c);
    }
    CP_COMMIT();

    auto issueK = [&](int n0, int ksub, int buf) {
        float* dst = Ks + buf * FK_F;
        #pragma unroll
        for (int i = 0; i < 4; i++) {
            int id = t + 256 * i;
            int r = id >> 3, c = (id & 7) * 4;
            cp16(&dst[r * FK_STRIDE + c],
                 Kg + (long long)(n0 + r) * DCAT + ksub * 32 + c);
        }
    };
    auto issueV = [&](int n0) {
        #pragma unroll
        for (int i = 0; i < 16; i++) {
            int id = t + 256 * i;
            int r = id >> 5, c = (id & 31) * 4;
            cp16(&Vs[r * FV_STRIDE + c], Vg + (long long)r * NN + n0 + c);
        }
    };

    issueK(0, 0, 0); issueV(0); CP_COMMIT();
    issueK(0, 1, 1); CP_COMMIT();

    float sacc[16][4], oacc[16][4];
    float mrun[2] = { -INFINITY, -INFINITY };
    float lrun[2] = { 0.f, 0.f };
    #pragma unroll
    for (int i = 0; i < 16; i++)
        #pragma unroll
        for (int q = 0; q < 4; q++) oacc[i][q] = 0.f;

    for (int chunk = 0; chunk < 16; chunk++) {
        const int n0 = chunk * 128;
        #pragma unroll
        for (int i = 0; i < 16; i++)
            #pragma unroll
            for (int q = 0; q < 4; q++) sacc[i][q] = 0.f;

        for (int ksub = 0; ksub < 6; ksub++) {
            if (ksub < 5) { CP_WAIT(1); } else { CP_WAIT(0); }
            __syncthreads();
            uint32_t Kb = ks_b + ((ksub & 1) * FK_F) * 4;
            #pragma unroll
            for (int kk = 0; kk < 4; kk++) {
                int qc = ksub * 32 + kk * 8;
                uint32_t af[4];
                ldm_x4(af, qs_b + ((rw + a_row) * FQ_STRIDE + qc + a_col) * 4);
                #pragma unroll
                for (int np = 0; np < 8; np++) {
                    uint32_t bf[4];
                    ldm_x4(bf, Kb + ((16 * np + b_row) * FK_STRIDE + kk * 8 + b_col) * 4);
                    mma_tf32(sacc[2 * np],     af[0], af[1], af[2], af[3], bf[0], bf[1]);
                    mma_tf32(sacc[2 * np + 1], af[0], af[1], af[2], af[3], bf[2], bf[3]);
                }
            }
            __syncthreads();
            if (ksub + 2 < 6) { issueK(n0, ksub + 2, ksub & 1); CP_COMMIT(); }
        }

        #pragma unroll
        for (int i = 0; i < 16; i++)
            #pragma unroll
            for (int q = 0; q < 4; q++) sacc[i][q] *= SCALE_F;

        #pragma unroll
        for (int h = 0; h < 2; h++) {
            float cm = -INFINITY;
            #pragma unroll
            for (int ni = 0; ni < 16; ni++)
                cm = fmaxf(cm, fmaxf(sacc[ni][2 * h], sacc[ni][2 * h + 1]));
            cm = fmaxf(cm, __shfl_xor_sync(0xFFFFFFFF, cm, 1));
            cm = fmaxf(cm, __shfl_xor_sync(0xFFFFFFFF, cm, 2));
            float mnew = fmaxf(mrun[h], cm);
            float alpha = __expf(mrun[h] - mnew);
            mrun[h] = mnew;
            float rs = 0.f;
            #pragma unroll
            for (int ni = 0; ni < 16; ni++) {
                float p0 = __expf(sacc[ni][2 * h] - mnew);
                float p1 = __expf(sacc[ni][2 * h + 1] - mnew);
                rs += p0 + p1;
                sacc[ni][2 * h]     = tf32r(p0);
                sacc[ni][2 * h + 1] = tf32r(p1);
            }
            rs += __shfl_xor_sync(0xFFFFFFFF, rs, 1);
            rs += __shfl_xor_sync(0xFFFFFFFF, rs, 2);
            lrun[h] = lrun[h] * alpha + rs;
            #pragma unroll
            for (int ni = 0; ni < 16; ni++) {
                oacc[ni][2 * h]     *= alpha;
                oacc[ni][2 * h + 1] *= alpha;
            }
        }

        #pragma unroll
        for (int s = 0; s < 16; s++) {
            int srcA = (fr << 2) | (fc >> 1);
            int srcB = srcA + 2;
            float x0 = __shfl_sync(0xFFFFFFFF, sacc[s][0], srcA);
            float x1 = __shfl_sync(0xFFFFFFFF, sacc[s][1], srcA);
            float y0 = __shfl_sync(0xFFFFFFFF, sacc[s][0], srcB);
            float y1 = __shfl_sync(0xFFFFFFFF, sacc[s][1], srcB);
            float z0 = __shfl_sync(0xFFFFFFFF, sacc[s][2], srcA);
            float z1 = __shfl_sync(0xFFFFFFFF, sacc[s][3], srcA);
            float w0 = __shfl_sync(0xFFFFFFFF, sacc[s][2], srcB);
            float w1 = __shfl_sync(0xFFFFFFFF, sacc[s][3], srcB);
            bool odd = (fc & 1);
            uint32_t a0 = __float_as_uint(odd ? x1 : x0);
            uint32_t a2 = __float_as_uint(odd ? y1 : y0);
            uint32_t a1 = __float_as_uint(odd ? z1 : z0);
            uint32_t a3 = __float_as_uint(odd ? w1 : w0);
            #pragma unroll
            for (int np = 0; np < 8; np++) {
                uint32_t bf[4];
                ldm_x4(bf, vs_b + ((16 * np + b_row) * FV_STRIDE + 8 * s + b_col) * 4);
                mma_tf32(oacc[2 * np],     a0, a1, a2, a3, bf[0], bf[1]);
                mma_tf32(oacc[2 * np + 1], a0, a1, a2, a3, bf[2], bf[3]);
            }
        }
        __syncthreads();
        if (chunk + 1 < 16) {
            issueK(n0 + 128, 0, 0); issueV(n0 + 128); CP_COMMIT();
            issueK(n0 + 128, 1, 1); CP_COMMIT();
        }
    }

    const int b  = bh >> 4;
    const int hd = bh & 15;
    float inv0 = 1.f / lrun[0];
    float inv1 = 1.f / lrun[1];
    int r0 = m0 + rw + fr;
    #pragma unroll
    for (int nj = 0; nj < 16; nj++) {
        int d = hd * DH + nj * 8 + 2 * fc;
        long long base0 = ((long long)(b * MM + r0)) * (HH * DH) + d;
        long long base1 = ((long long)(b * MM + r0 + 8)) * (HH * DH) + d;
        Ctx[base0]     = tf32r(oacc[nj][0] * inv0);
        Ctx[base0 + 1] = tf32r(oacc[nj][1] * inv0);
        Ctx[base1]     = tf32r(oacc[nj][2] * inv1);
        Ctx[base1 + 1] = tf32r(oacc[nj][3] * inv1);
    }
}

// -------------------- launch --------------------
extern "C" void kernel_launch(void* const* d_in, const int* in_sizes, int n_in,
                              void* d_out, int out_size) {
    const float* query = (const float*)d_in[0];
    const float* kv    = (const float*)d_in[1];
    const float* W_QC  = (const float*)d_in[2];
    const float* W_KC  = (const float*)d_in[3];
    const float* W_QR  = (const float*)d_in[4];
    const float* W_KR  = (const float*)d_in[5];
    const float* W_V   = (const float*)d_in[6];
    const float* W_O   = (const float*)d_in[7];
    float* out = (float*)d_out;

    float *Qcat, *Kcat, *Vt, *Ctx, *cq, *ckv, *wq, *wkv, *wo;
    cudaGetSymbolAddress((void**)&Qcat, g_Qcat);
    cudaGetSymbolAddress((void**)&Kcat, g_Kcat);
    cudaGetSymbolAddress((void**)&Vt,   g_Vt);
    cudaGetSymbolAddress((void**)&Ctx,  g_Ctx);
    cudaGetSymbolAddress((void**)&cq,   g_cq);
    cudaGetSymbolAddress((void**)&ckv,  g_ckv);
    cudaGetSymbolAddress((void**)&wq,   g_wq);
    cudaGetSymbolAddress((void**)&wkv,  g_wkv);
    cudaGetSymbolAddress((void**)&wo,   g_wo);

    cudaFuncSetAttribute(mma_gemm<EPI_Q,    true>,  cudaFuncAttributeMaxDynamicSharedMemorySize, SMEM_BYTES);
    cudaFuncSetAttribute(mma_gemm<EPI_KV,   true>,  cudaFuncAttributeMaxDynamicSharedMemorySize, SMEM_BYTES);
    cudaFuncSetAttribute(mma_gemm<EPI_PLAIN,false>, cudaFuncAttributeMaxDynamicSharedMemorySize, SMEM_BYTES);
    cudaFuncSetAttribute(flash_kernel, cudaFuncAttributeMaxDynamicSharedMemorySize, FL_SMEM_BYTES);

    // ---- rope cos/sin table (once, tiny) ----
    rope_table_kernel<<<(MM * 32) / 256, 256>>>();

    // ---- single merged tf32-round prepass (weights land stacked) ----
    ConvArgs ca;
    ca.src[0] = (const float4*)query; ca.dst[0] = (float4*)cq;   ca.n4[0] = BB*MM*DD/4;
    ca.src[1] = (const float4*)kv;    ca.dst[1] = (float4*)ckv;  ca.n4[1] = BB*NN*DD/4;
    ca.src[2] = (const float4*)W_QC;  ca.dst[2] = (float4*)wq;                          ca.n4[2] = HH*DH*DD/4;
    ca.src[3] = (const float4*)W_QR;  ca.dst[3] = (float4*)(wq + (long long)HH*DH*DD);  ca.n4[3] = HH*DR*DD/4;
    ca.src[4] = (const float4*)W_KC;  ca.dst[4] = (float4*)wkv;                         ca.n4[4] = HH*DH*DD/4;
    ca.src[5] = (const float4*)W_KR;  ca.dst[5] = (float4*)(wkv + (long long)HH*DH*DD); ca.n4[5] = HH*DR*DD/4;
    ca.src[6] = (const float4*)W_V;   ca.dst[6] = (float4*)(wkv + (long long)(HH*DH + HH*DR)*DD); ca.n4[6] = HH*DH*DD/4;
    ca.src[7] = (const float4*)W_O;   ca.dst[7] = (float4*)wo;   ca.n4[7] = DD*HH*DH/4;
    {
        int maxn4 = BB*MM*DD/4;
        conv8_kernel<<<dim3((maxn4 + 255) / 256, 8), 256>>>(ca);
    }

    dim3 gblk(128);

    // ---- merged projections (RoPE fused into epilogue) ----
    mma_gemm<EPI_Q, true><<<dim3(3072 / 128, (BB * MM) / 128), gblk, SMEM_BYTES>>>(
        cq, DD, wq, DD, Qcat, nullptr, 0, DD);
    mma_gemm<EPI_KV, true><<<dim3(5120 / 128, (BB * NN) / 128), gblk, SMEM_BYTES>>>(
        ckv, DD, wkv, DD, Kcat, Vt, 0, DD);

    // ---- fused flash attention ----
    flash_kernel<<<dim3(MM / 128, BB * HH), 256, FL_SMEM_BYTES>>>(Qcat, Kcat, Vt, Ctx);

    // ---- output projection ----
    mma_gemm<EPI_PLAIN, false><<<dim3(DD / 128, (BB * MM) / 128), gblk, SMEM_BYTES>>>(
        Ctx, HH * DH, wo, DD, out, nullptr, DD, HH * DH);
}